// round 4
// baseline (speedup 1.0000x reference)
#include <cuda_runtime.h>
#include <cstdint>

#define NTREES 256
#define NPT    1024
#define NN     (NTREES * NPT)          // 262144 nodes
#define VOCAB  5000
#define SORTV  64
#define NPOS   1024
#define TCOLS  512                     // 384 iou cols + 128 f cols
#define BM     64
#define PAD    132                     // padded row stride for A tiles (conflict-free frags)

// smem layout (floats): sHL[64*132], sHR, sHS, sIOU[64*384]
#define OFF_HL  0
#define OFF_HR  (64 * PAD)
#define OFF_HS  (2 * 64 * PAD)
#define OFF_IOU (3 * 64 * PAD)
#define SMEMF   (3 * 64 * PAD + 64 * 384)
#define SMEMSZ  (SMEMF * 4)            // 199680 bytes

// Scratch (device globals: allocation-free per harness rules)
__device__ float g_h[NN * 128];        // 128 MB
__device__ float g_c[NN * 128];        // 128 MB
__device__ float g_Ttok[VOCAB * TCOLS];
__device__ float g_Tsort[SORTV * TCOLS];
__device__ float g_Tpos[NPOS * TCOLS];
__device__ float g_Upk[64 * 16 * 64]; // packed tf32 B fragments: [nf(64)][ks(16)][64 words]
__device__ int   g_is64;               // 1 if features buffer is int64, 0 if int32

__device__ __forceinline__ float sigf(float x) { return 1.0f / (1.0f + __expf(-x)); }
__device__ __forceinline__ float4 sig4(float4 a, float4 p) {
    return make_float4(sigf(a.x + p.x), sigf(a.y + p.y), sigf(a.z + p.z), sigf(a.w + p.w));
}
__device__ __forceinline__ uint32_t f2tf32(float f) {
    uint32_t r;
    asm("cvt.rna.tf32.f32 %0, %1;" : "=r"(r) : "f"(f));
    return r;
}

// Feature fetch that works for either int32 or int64 feature buffers.
__device__ __forceinline__ int3 getfeat(const void* f, int g)
{
    if (g_is64) {
        const long long* p = (const long long*)f;
        return make_int3((int)p[3 * g], (int)p[3 * g + 1], (int)p[3 * g + 2]);
    }
    const int* p = (const int*)f;
    return make_int3(p[3 * g], p[3 * g + 1], p[3 * g + 2]);
}

// ---------------------------------------------------------------------------
// Dtype detection: int64 buffer (values < 2^31) has every odd 32-bit word 0.
// ---------------------------------------------------------------------------
__global__ void kd_init() { g_is64 = 1; }

__global__ void kd_detect(const int* f)
{
    int idx = (blockIdx.x * 256 + threadIdx.x) * 2 + 1;
    if (idx < 3 * NN && f[idx] != 0) atomicExch(&g_is64, 0);
}

// ---------------------------------------------------------------------------
// K0: projection tables. T_tok = emb@W[0:64], T_sort = sort@W[64:128],
// T_pos = pe@W[128:192] + bias, where W = [W_iou | W_f] (512 cols).
// ---------------------------------------------------------------------------
__global__ void k0_tables(const float* __restrict__ emb,
                          const float* __restrict__ sortt,
                          const float* __restrict__ pe,
                          const float* __restrict__ Wiou,
                          const float* __restrict__ Wf,
                          const float* __restrict__ biou,
                          const float* __restrict__ bf)
{
    __shared__ float se[8][64];
    int b = blockIdx.x;
    int j = threadIdx.x;   // output column

    const float* src; int wbase; float* dst; bool addb;
    if (b < 625)      { int r0 = b * 8;         src = emb   + r0 * 64; wbase = 0;   dst = g_Ttok  + r0 * TCOLS; addb = false; }
    else if (b < 633) { int r0 = (b - 625) * 8; src = sortt + r0 * 64; wbase = 64;  dst = g_Tsort + r0 * TCOLS; addb = false; }
    else              { int r0 = (b - 633) * 8; src = pe    + r0 * 64; wbase = 128; dst = g_Tpos  + r0 * TCOLS; addb = true;  }

    se[j >> 6][j & 63] = src[j];
    __syncthreads();

    float acc[8];
#pragma unroll
    for (int r = 0; r < 8; r++) acc[r] = 0.0f;

    float bias = 0.0f;
    if (j < 384) {
#pragma unroll 8
        for (int k = 0; k < 64; k++) {
            float w = Wiou[(wbase + k) * 384 + j];
#pragma unroll
            for (int r = 0; r < 8; r++) acc[r] += se[r][k] * w;
        }
        if (addb) bias = biou[j];
    } else {
        int jj = j - 384;
#pragma unroll 8
        for (int k = 0; k < 64; k++) {
            float w = Wf[(wbase + k) * 128 + jj];
#pragma unroll
            for (int r = 0; r < 8; r++) acc[r] += se[r][k] * w;
        }
        if (addb) bias = bf[jj];
    }
#pragma unroll
    for (int r = 0; r < 8; r++) dst[r * TCOLS + j] = acc[r] + bias;
}

// ---------------------------------------------------------------------------
// K0b: pack U = [U_iou | U_f] into mma-fragment order (tf32-rounded).
// Fragment (nf, ks): word w: lane=w>>1, half=w&1,
//   k = 8*ks + (lane&3) + 4*half, col = 8*nf + (lane>>2).
// nf 0..47 -> U_iou, 48..63 -> U_f.
// Each thread's b-pair for mma is then one coalesced 8-byte load.
// ---------------------------------------------------------------------------
__global__ void k0b_pack(const float* __restrict__ Uiou, const float* __restrict__ Uf)
{
    int idx = blockIdx.x * 256 + threadIdx.x;   // 0..65535
    int f = idx >> 6, w = idx & 63;
    int nf = f >> 4, ks = f & 15;
    int lane = w >> 1, half = w & 1;
    int k = 8 * ks + (lane & 3) + 4 * half;
    int c = lane >> 2;
    float v = (nf < 48) ? Uiou[k * 384 + nf * 8 + c]
                        : Uf[k * 128 + (nf - 48) * 8 + c];
    ((uint32_t*)g_Upk)[idx] = f2tf32(v);
}

// ---------------------------------------------------------------------------
// K1: leaves. iou = P only; c = sig(i)*tanh(u); h = sig(o)*tanh(c)
// ---------------------------------------------------------------------------
__global__ void k1_leaves(const void* __restrict__ feats)
{
    int tid = threadIdx.x;
    int j   = tid & 127;
    int L   = blockIdx.x * 2 + (tid >> 7);
    int t   = L >> 9;
    int i   = 512 + (L & 511);
    int g   = t * NPT + i;

    int3 ft = getfeat(feats, g);

    const float* Pt = g_Ttok  + ft.x * TCOLS;
    const float* Ps = g_Tsort + ft.y * TCOLS;
    const float* Pp = g_Tpos  + ft.z * TCOLS;

    float pi = Pt[j]       + Ps[j]       + Pp[j];
    float po = Pt[128 + j] + Ps[128 + j] + Pp[128 + j];
    float pu = Pt[256 + j] + Ps[256 + j] + Pp[256 + j];

    float c = sigf(pi) * tanhf(pu);
    float h = sigf(po) * tanhf(c);
    g_c[g * 128 + j] = c;
    g_h[g * 128 + j] = h;
}

// ---------------------------------------------------------------------------
// 16x64 warp tile: C[16x64] += A[16x128] @ B[128x64] via m16n8k8 tf32 mma.
// A from smem (row stride PAD), B fragments from g_Upk (coalesced LDG.64).
// ---------------------------------------------------------------------------
__device__ __forceinline__ void mma_tile(const float* __restrict__ sA, int nf0,
                                         int lane, float acc[8][4])
{
    int g = lane >> 2, tg = lane & 3;
    const float* ar0 = sA + g * PAD;
    const float* ar1 = sA + (g + 8) * PAD;
#pragma unroll
    for (int nf = 0; nf < 8; nf++)
        acc[nf][0] = acc[nf][1] = acc[nf][2] = acc[nf][3] = 0.0f;

#pragma unroll 4
    for (int ks = 0; ks < 16; ks++) {
        uint32_t a0 = f2tf32(ar0[8 * ks + tg]);
        uint32_t a1 = f2tf32(ar1[8 * ks + tg]);
        uint32_t a2 = f2tf32(ar0[8 * ks + tg + 4]);
        uint32_t a3 = f2tf32(ar1[8 * ks + tg + 4]);
        const float* bp = g_Upk + (nf0 * 16 + ks) * 64 + 2 * lane;
#pragma unroll
        for (int nf = 0; nf < 8; nf++) {
            uint2 b = *(const uint2*)(bp + nf * 1024);
            asm volatile(
                "mma.sync.aligned.m16n8k8.row.col.f32.tf32.tf32.f32 "
                "{%0,%1,%2,%3}, {%4,%5,%6,%7}, {%8,%9}, {%0,%1,%2,%3};\n"
                : "+f"(acc[nf][0]), "+f"(acc[nf][1]), "+f"(acc[nf][2]), "+f"(acc[nf][3])
                : "r"(a0), "r"(a1), "r"(a2), "r"(a3), "r"(b.x), "r"(b.y));
        }
    }
}

// ---------------------------------------------------------------------------
// K2: one internal level via tensor cores. BM=64 nodes/block, 256 threads.
// ---------------------------------------------------------------------------
__global__ __launch_bounds__(256) void k2_mma(
    const void* __restrict__ feats,
    float* __restrict__ out,
    int beg, int cnt)
{
    extern __shared__ float sm[];
    float* sHL  = sm + OFF_HL;
    float* sHR  = sm + OFF_HR;
    float* sHS  = sm + OFF_HS;
    float* sIOU = sm + OFF_IOU;        // [64][384] raw iou, then slot reuse

    __shared__ int sg[BM], sgl[BM], sgr[BM], stok[BM], ssrt[BM], spos[BM];

    int tid  = threadIdx.x;
    int lane = tid & 31;
    int w    = tid >> 5;               // warp 0..7
    int mt   = w & 3;                  // m-tile (16 nodes)
    int cs   = w >> 2;                 // col-strip / child select

    if (tid < BM) {
        int m = blockIdx.x * BM + tid;
        int t = m / cnt, i = beg + m % cnt;
        int g = t * NPT + i;
        sg[tid]  = g;
        sgl[tid] = t * NPT + 2 * i + 1;
        int rr = 2 * i + 2;
        sgr[tid] = (rr < NPT) ? t * NPT + rr : -1;
        int3 ft = getfeat(feats, g);
        stok[tid] = ft.x;
        ssrt[tid] = ft.y;
        spos[tid] = ft.z;
    }
    __syncthreads();

    // Stage child h tiles + sum (padded rows)
#pragma unroll
    for (int r4 = 0; r4 < 8; r4++) {
        int idx = tid + r4 * 256;      // 0..2047 = m*32 + q
        int m = idx >> 5, q = idx & 31;
        float4 hl = *(const float4*)&g_h[sgl[m] * 128 + q * 4];
        float4 hr = make_float4(0.f, 0.f, 0.f, 0.f);
        int gr = sgr[m];
        if (gr >= 0) hr = *(const float4*)&g_h[gr * 128 + q * 4];
        *(float4*)&sHL[m * PAD + q * 4] = hl;
        *(float4*)&sHR[m * PAD + q * 4] = hr;
        *(float4*)&sHS[m * PAD + q * 4] =
            make_float4(hl.x + hr.x, hl.y + hr.y, hl.z + hr.z, hl.w + hr.w);
    }
    __syncthreads();

    int g4 = lane >> 2, tg = lane & 3;
    float acc[8][4];

    // ---- Phase 1: iou = hs @ U_iou (raw, into sIOU) ----
    const float* Ahs = sHS + mt * 16 * PAD;
#pragma unroll 1
    for (int s = 0; s < 3; s++) {
        int nb = cs * 192 + s * 64;    // column base
        mma_tile(Ahs, nb >> 3, lane, acc);
#pragma unroll
        for (int nf = 0; nf < 8; nf++) {
            int col = nb + nf * 8 + 2 * tg;
            *(float2*)&sIOU[(mt * 16 + g4) * 384 + col]     = make_float2(acc[nf][0], acc[nf][1]);
            *(float2*)&sIOU[(mt * 16 + g4 + 8) * 384 + col] = make_float2(acc[nf][2], acc[nf][3]);
        }
    }
    __syncthreads();

    // ---- Epilogue A: c0 = sig(i+Pi)*tanh(u+Pu) -> u slot; sig(o+Po) -> o slot.
    //      i slot becomes free.
#pragma unroll 1
    for (int it = 0; it < 8; it++) {
        int idx = tid + it * 256;
        int m = idx >> 5, q = idx & 31;
        const float* Pt = g_Ttok  + stok[m] * TCOLS + q * 4;
        const float* Ps = g_Tsort + ssrt[m] * TCOLS + q * 4;
        const float* Pp = g_Tpos  + spos[m] * TCOLS + q * 4;
        float* row = sIOU + m * 384 + q * 4;

        float4 ri = *(float4*)row;
        float4 ro = *(float4*)(row + 128);
        float4 ru = *(float4*)(row + 256);
        float4 a, b, d, pi, po, pu;
        a = *(const float4*)Pt;         b = *(const float4*)Ps;         d = *(const float4*)Pp;
        pi = make_float4(a.x+b.x+d.x, a.y+b.y+d.y, a.z+b.z+d.z, a.w+b.w+d.w);
        a = *(const float4*)(Pt+128);   b = *(const float4*)(Ps+128);   d = *(const float4*)(Pp+128);
        po = make_float4(a.x+b.x+d.x, a.y+b.y+d.y, a.z+b.z+d.z, a.w+b.w+d.w);
        a = *(const float4*)(Pt+256);   b = *(const float4*)(Ps+256);   d = *(const float4*)(Pp+256);
        pu = make_float4(a.x+b.x+d.x, a.y+b.y+d.y, a.z+b.z+d.z, a.w+b.w+d.w);

        float4 si = sig4(ri, pi);
        float4 so = sig4(ro, po);
        float4 c0 = make_float4(si.x * tanhf(ru.x + pu.x), si.y * tanhf(ru.y + pu.y),
                                si.z * tanhf(ru.z + pu.z), si.w * tanhf(ru.w + pu.w));
        *(float4*)(row + 256) = c0;    // u slot := c0
        *(float4*)(row + 128) = so;    // o slot := sig(o)
    }
    __syncthreads();

    // ---- Phase 2: f gates. warps cs=0: fl=hl@Uf -> i slot; cs=1: fr=hr@Uf -> sHS (dead).
    {
        const float* Af = (cs ? sHR : sHL) + mt * 16 * PAD;
#pragma unroll 1
        for (int s = 0; s < 2; s++) {
            mma_tile(Af, 48 + s * 8, lane, acc);
#pragma unroll
            for (int nf = 0; nf < 8; nf++) {
                int col = s * 64 + nf * 8 + 2 * tg;
                if (cs == 0) {
                    *(float2*)&sIOU[(mt * 16 + g4) * 384 + col]     = make_float2(acc[nf][0], acc[nf][1]);
                    *(float2*)&sIOU[(mt * 16 + g4 + 8) * 384 + col] = make_float2(acc[nf][2], acc[nf][3]);
                } else {
                    *(float2*)&sHS[(mt * 16 + g4) * 128 + col]      = make_float2(acc[nf][0], acc[nf][1]);
                    *(float2*)&sHS[(mt * 16 + g4 + 8) * 128 + col]  = make_float2(acc[nf][2], acc[nf][3]);
                }
            }
        }
    }
    __syncthreads();

    // ---- Epilogue B: c = c0 + sig(fl+Pf)*cl + sig(fr+Pf)*cr ; h = sig_o*tanh(c)
#pragma unroll 1
    for (int it = 0; it < 8; it++) {
        int idx = tid + it * 256;
        int m = idx >> 5, q = idx & 31;
        float* row = sIOU + m * 384 + q * 4;
        float4 fl = *(float4*)row;                 // i slot
        float4 fr = *(float4*)&sHS[m * 128 + q * 4];
        float4 so = *(float4*)(row + 128);
        float4 c0 = *(float4*)(row + 256);

        int off = 384 + q * 4;
        float4 a = *(const float4*)&g_Ttok[stok[m] * TCOLS + off];
        float4 b = *(const float4*)&g_Tsort[ssrt[m] * TCOLS + off];
        float4 d = *(const float4*)&g_Tpos[spos[m] * TCOLS + off];
        float4 pf = make_float4(a.x+b.x+d.x, a.y+b.y+d.y, a.z+b.z+d.z, a.w+b.w+d.w);

        float4 cl = *(const float4*)&g_c[sgl[m] * 128 + q * 4];
        float4 cr = make_float4(0.f, 0.f, 0.f, 0.f);
        int gr = sgr[m];
        if (gr >= 0) cr = *(const float4*)&g_c[gr * 128 + q * 4];

        float4 sfl = sig4(fl, pf);
        float4 sfr = sig4(fr, pf);
        float4 cv = make_float4(c0.x + sfl.x * cl.x + sfr.x * cr.x,
                                c0.y + sfl.y * cl.y + sfr.y * cr.y,
                                c0.z + sfl.z * cl.z + sfr.z * cr.z,
                                c0.w + sfl.w * cl.w + sfr.w * cr.w);
        float4 hv = make_float4(so.x * tanhf(cv.x), so.y * tanhf(cv.y),
                                so.z * tanhf(cv.z), so.w * tanhf(cv.w));
        int gg = sg[m];
        *(float4*)&g_c[gg * 128 + q * 4] = cv;
        *(float4*)&g_h[gg * 128 + q * 4] = hv;
        if (out) *(float4*)&out[(gg >> 10) * 128 + q * 4] = hv;
    }
}

// ---------------------------------------------------------------------------
extern "C" void kernel_launch(void* const* d_in, const int* in_sizes, int n_in,
                              void* d_out, int out_size)
{
    const void* feats  = d_in[0];
    const float* emb   = (const float*)d_in[4];
    const float* sortt = (const float*)d_in[5];
    const float* pe    = (const float*)d_in[6];
    const float* Wiou  = (const float*)d_in[7];
    const float* Uiou  = (const float*)d_in[8];
    const float* biou  = (const float*)d_in[9];
    const float* Wf    = (const float*)d_in[10];
    const float* Uf    = (const float*)d_in[11];
    const float* bf    = (const float*)d_in[12];
    float* out = (float*)d_out;

    cudaFuncSetAttribute(k2_mma, cudaFuncAttributeMaxDynamicSharedMemorySize, SMEMSZ);

    // dtype detect + tables + packed U + leaves
    kd_init<<<1, 1>>>();
    kd_detect<<<(3 * NN / 2 + 255) / 256, 256>>>((const int*)feats);
    k0_tables<<<761, 512>>>(emb, sortt, pe, Wiou, Wf, biou, bf);
    k0b_pack<<<256, 256>>>(Uiou, Uf);
    k1_leaves<<<65536, 256>>>(feats);

    // internal levels bottom-up: l=1 is node 511 (single child), then l=2..10
    k2_mma<<<NTREES / BM, 256, SMEMSZ>>>(feats, nullptr, 511, 1);
    for (int l = 2; l <= 10; l++) {
        int cnt = 1 << (10 - l);
        k2_mma<<<NTREES * cnt / BM, 256, SMEMSZ>>>(feats,
                                                   (l == 10) ? out : nullptr,
                                                   cnt - 1, cnt);
    }
}

// round 5
// speedup vs baseline: 1.4075x; 1.4075x over previous
#include <cuda_runtime.h>
#include <cstdint>

#define NTREES 256
#define NPT    1024
#define NN     (NTREES * NPT)          // 262144 nodes
#define VOCAB  5000
#define SORTV  64
#define NPOS   1024
#define TCOLS  512                     // 384 iou cols + 128 f cols
#define BM     64
#define PAD    132                     // padded row stride (conflict-free A frags)

// smem (uint32 tf32 bits): sHL[64*132], sHR, sHS
#define OFF_HL  0
#define OFF_HR  (64 * PAD)
#define OFF_HS  (2 * 64 * PAD)
#define SMEMSZ  (3 * 64 * PAD * 4)     // 101376 bytes

// Device-global scratch (allocation-free per harness rules)
__device__ float    g_h[NN * 128];     // 128 MB
__device__ float    g_c[NN * 128];     // 128 MB
__device__ float    g_Ttok[VOCAB * TCOLS];
__device__ float    g_Tsort[SORTV * TCOLS];
__device__ float    g_Tpos[NPOS * TCOLS];
__device__ unsigned g_Upk[64 * 16 * 64];  // tf32 B frags: [nf(64)][ks(16)][64 words]
__device__ int      g_is64;

__device__ __forceinline__ float sigf(float x) { return 1.0f / (1.0f + __expf(-x)); }
__device__ __forceinline__ uint32_t f2tf32(float f) {
    uint32_t r;
    asm("cvt.rna.tf32.f32 %0, %1;" : "=r"(r) : "f"(f));
    return r;
}
__device__ __forceinline__ uint4 cvt4(float4 v) {
    return make_uint4(f2tf32(v.x), f2tf32(v.y), f2tf32(v.z), f2tf32(v.w));
}

#define MMA(ACC, A0, A1, A2, A3, B)                                            \
    asm volatile(                                                              \
        "mma.sync.aligned.m16n8k8.row.col.f32.tf32.tf32.f32 "                  \
        "{%0,%1,%2,%3}, {%4,%5,%6,%7}, {%8,%9}, {%0,%1,%2,%3};\n"              \
        : "+f"(ACC[0]), "+f"(ACC[1]), "+f"(ACC[2]), "+f"(ACC[3])               \
        : "r"(A0), "r"(A1), "r"(A2), "r"(A3), "r"(B.x), "r"(B.y))

// Feature fetch for int32 or int64 feature buffers.
__device__ __forceinline__ int3 getfeat(const void* f, int g)
{
    if (g_is64) {
        const long long* p = (const long long*)f;
        return make_int3((int)p[3 * g], (int)p[3 * g + 1], (int)p[3 * g + 2]);
    }
    const int* p = (const int*)f;
    return make_int3(p[3 * g], p[3 * g + 1], p[3 * g + 2]);
}

// ---------------------------------------------------------------------------
__global__ void kd_init() { g_is64 = 1; }
__global__ void kd_detect(const int* f)
{
    int idx = (blockIdx.x * 256 + threadIdx.x) * 2 + 1;
    if (idx < 3 * NN && f[idx] != 0) atomicExch(&g_is64, 0);
}

// ---------------------------------------------------------------------------
// K0: projection tables (embedding @ W factored through the three tables).
// ---------------------------------------------------------------------------
__global__ void k0_tables(const float* __restrict__ emb,
                          const float* __restrict__ sortt,
                          const float* __restrict__ pe,
                          const float* __restrict__ Wiou,
                          const float* __restrict__ Wf,
                          const float* __restrict__ biou,
                          const float* __restrict__ bf)
{
    __shared__ float se[8][64];
    int b = blockIdx.x;
    int j = threadIdx.x;

    const float* src; int wbase; float* dst; bool addb;
    if (b < 625)      { int r0 = b * 8;         src = emb   + r0 * 64; wbase = 0;   dst = g_Ttok  + r0 * TCOLS; addb = false; }
    else if (b < 633) { int r0 = (b - 625) * 8; src = sortt + r0 * 64; wbase = 64;  dst = g_Tsort + r0 * TCOLS; addb = false; }
    else              { int r0 = (b - 633) * 8; src = pe    + r0 * 64; wbase = 128; dst = g_Tpos  + r0 * TCOLS; addb = true;  }

    se[j >> 6][j & 63] = src[j];
    __syncthreads();

    float acc[8];
#pragma unroll
    for (int r = 0; r < 8; r++) acc[r] = 0.0f;

    float bias = 0.0f;
    if (j < 384) {
#pragma unroll 8
        for (int k = 0; k < 64; k++) {
            float w = Wiou[(wbase + k) * 384 + j];
#pragma unroll
            for (int r = 0; r < 8; r++) acc[r] += se[r][k] * w;
        }
        if (addb) bias = biou[j];
    } else {
        int jj = j - 384;
#pragma unroll 8
        for (int k = 0; k < 64; k++) {
            float w = Wf[(wbase + k) * 128 + jj];
#pragma unroll
            for (int r = 0; r < 8; r++) acc[r] += se[r][k] * w;
        }
        if (addb) bias = bf[jj];
    }
#pragma unroll
    for (int r = 0; r < 8; r++) dst[r * TCOLS + j] = acc[r] + bias;
}

// ---------------------------------------------------------------------------
// K0b: pack U = [U_iou | U_f] into m16n8k8 B-fragment order (tf32 bits).
// ---------------------------------------------------------------------------
__global__ void k0b_pack(const float* __restrict__ Uiou, const float* __restrict__ Uf)
{
    int idx = blockIdx.x * 256 + threadIdx.x;   // 0..65535
    int f = idx >> 6, w = idx & 63;
    int nf = f >> 4, ks = f & 15;
    int lane = w >> 1, half = w & 1;
    int k = 8 * ks + (lane & 3) + 4 * half;
    int c = lane >> 2;
    float v = (nf < 48) ? Uiou[k * 384 + nf * 8 + c]
                        : Uf[k * 128 + (nf - 48) * 8 + c];
    g_Upk[idx] = f2tf32(v);
}

// ---------------------------------------------------------------------------
// K1: leaves, float4-vectorized. 256 threads = 8 leaves x 32 cols4.
// ---------------------------------------------------------------------------
__global__ void k1_leaves(const void* __restrict__ feats)
{
    int tid = threadIdx.x;
    int q   = tid & 31;                   // col group (4 floats)
    int L   = blockIdx.x * 8 + (tid >> 5);
    int t   = L >> 9;
    int i   = 512 + (L & 511);
    int g   = t * NPT + i;

    int3 ft = getfeat(feats, g);

    const float* Pt = g_Ttok  + ft.x * TCOLS + q * 4;
    const float* Ps = g_Tsort + ft.y * TCOLS + q * 4;
    const float* Pp = g_Tpos  + ft.z * TCOLS + q * 4;

    float4 a, b, d, pi, po, pu;
    a = *(const float4*)Pt;        b = *(const float4*)Ps;        d = *(const float4*)Pp;
    pi = make_float4(a.x+b.x+d.x, a.y+b.y+d.y, a.z+b.z+d.z, a.w+b.w+d.w);
    a = *(const float4*)(Pt+128);  b = *(const float4*)(Ps+128);  d = *(const float4*)(Pp+128);
    po = make_float4(a.x+b.x+d.x, a.y+b.y+d.y, a.z+b.z+d.z, a.w+b.w+d.w);
    a = *(const float4*)(Pt+256);  b = *(const float4*)(Ps+256);  d = *(const float4*)(Pp+256);
    pu = make_float4(a.x+b.x+d.x, a.y+b.y+d.y, a.z+b.z+d.z, a.w+b.w+d.w);

    float4 cv = make_float4(sigf(pi.x) * tanhf(pu.x), sigf(pi.y) * tanhf(pu.y),
                            sigf(pi.z) * tanhf(pu.z), sigf(pi.w) * tanhf(pu.w));
    float4 hv = make_float4(sigf(po.x) * tanhf(cv.x), sigf(po.y) * tanhf(cv.y),
                            sigf(po.z) * tanhf(cv.z), sigf(po.w) * tanhf(cv.w));
    *(float4*)&g_c[g * 128 + q * 4] = cv;
    *(float4*)&g_h[g * 128 + q * 4] = hv;
}

// ---------------------------------------------------------------------------
// K2: one internal level. BM=64 nodes/block, 256 threads, 2 blocks/SM.
// Warp item = 32 nodes x 8 cols; 5 gate accumulators in registers;
// epilogue entirely register-resident.
// ---------------------------------------------------------------------------
__global__ __launch_bounds__(256, 2) void k2_mma(
    const void* __restrict__ feats,
    float* __restrict__ out,
    int beg, int cnt)
{
    extern __shared__ unsigned smu[];
    unsigned* sHL = smu + OFF_HL;
    unsigned* sHR = smu + OFF_HR;
    unsigned* sHS = smu + OFF_HS;

    __shared__ int sg[BM], sgl[BM], sgr[BM], stok[BM], ssrt[BM], spos[BM];

    int tid  = threadIdx.x;
    int lane = tid & 31;
    int w    = tid >> 5;
    int g4   = lane >> 2, tg = lane & 3;

    if (tid < BM) {
        int m = blockIdx.x * BM + tid;
        int t = m / cnt, i = beg + m % cnt;
        int g = t * NPT + i;
        sg[tid]  = g;
        sgl[tid] = t * NPT + 2 * i + 1;
        int rr = 2 * i + 2;
        sgr[tid] = (rr < NPT) ? t * NPT + rr : -1;
        int3 ft = getfeat(feats, g);
        stok[tid] = ft.x;
        ssrt[tid] = ft.y;
        spos[tid] = ft.z;
    }
    __syncthreads();

    // Stage child h tiles as tf32 bits (hl, hr, hs=hl+hr)
#pragma unroll
    for (int r4 = 0; r4 < 8; r4++) {
        int idx = tid + r4 * 256;      // = m*32 + q
        int m = idx >> 5, q = idx & 31;
        float4 hl = *(const float4*)&g_h[sgl[m] * 128 + q * 4];
        float4 hr = make_float4(0.f, 0.f, 0.f, 0.f);
        int gr = sgr[m];
        if (gr >= 0) hr = *(const float4*)&g_h[gr * 128 + q * 4];
        *(uint4*)&sHL[m * PAD + q * 4] = cvt4(hl);
        *(uint4*)&sHR[m * PAD + q * 4] = cvt4(hr);
        *(uint4*)&sHS[m * PAD + q * 4] =
            cvt4(make_float4(hl.x + hr.x, hl.y + hr.y, hl.z + hr.z, hl.w + hr.w));
    }
    __syncthreads();

    // 4 items per warp: it = w + 8r;  mp = it>>4 (32-node half), cg = it&15 (8-col group)
#pragma unroll 1
    for (int r = 0; r < 4; r++) {
        int it = w + 8 * r;
        int mp = it >> 4, cg = it & 15;
        int mbase = mp * 32;

        float accI[2][4], accO[2][4], accU[2][4], accFL[2][4], accFR[2][4];
#pragma unroll
        for (int mt = 0; mt < 2; mt++)
#pragma unroll
            for (int e = 0; e < 4; e++) {
                accI[mt][e] = accO[mt][e] = accU[mt][e] = 0.0f;
                accFL[mt][e] = accFR[mt][e] = 0.0f;
            }

#pragma unroll 2
        for (int ks = 0; ks < 16; ks++) {
            uint2 bi = *(const uint2*)&g_Upk[((cg     ) * 16 + ks) * 64 + 2 * lane];
            uint2 bo = *(const uint2*)&g_Upk[((16 + cg) * 16 + ks) * 64 + 2 * lane];
            uint2 bu = *(const uint2*)&g_Upk[((32 + cg) * 16 + ks) * 64 + 2 * lane];
            uint2 bf = *(const uint2*)&g_Upk[((48 + cg) * 16 + ks) * 64 + 2 * lane];
#pragma unroll
            for (int mt = 0; mt < 2; mt++) {
                int rowoff = (mbase + mt * 16 + g4) * PAD + 8 * ks + tg;
                unsigned s0 = sHS[rowoff],           s1 = sHS[rowoff + 8 * PAD];
                unsigned s2 = sHS[rowoff + 4],       s3 = sHS[rowoff + 8 * PAD + 4];
                MMA(accI[mt], s0, s1, s2, s3, bi);
                MMA(accO[mt], s0, s1, s2, s3, bo);
                MMA(accU[mt], s0, s1, s2, s3, bu);
                unsigned l0 = sHL[rowoff],           l1 = sHL[rowoff + 8 * PAD];
                unsigned l2 = sHL[rowoff + 4],       l3 = sHL[rowoff + 8 * PAD + 4];
                MMA(accFL[mt], l0, l1, l2, l3, bf);
                unsigned r0 = sHR[rowoff],           r1 = sHR[rowoff + 8 * PAD];
                unsigned r2 = sHR[rowoff + 4],       r3 = sHR[rowoff + 8 * PAD + 4];
                MMA(accFR[mt], r0, r1, r2, r3, bf);
            }
        }

        // Register epilogue: rows m = mbase + mt*16 + rr*8 + g4, cols c0, c0+1.
        int c0 = cg * 8 + 2 * tg;
#pragma unroll
        for (int mt = 0; mt < 2; mt++)
#pragma unroll
            for (int rr = 0; rr < 2; rr++) {
                int m = mbase + mt * 16 + rr * 8 + g4;
                int a = rr * 2;
                const float* Tt = g_Ttok  + stok[m] * TCOLS + c0;
                const float* Ts = g_Tsort + ssrt[m] * TCOLS + c0;
                const float* Tp = g_Tpos  + spos[m] * TCOLS + c0;

                float2 t0, t1, t2;
                t0 = *(const float2*)Tt;        t1 = *(const float2*)Ts;        t2 = *(const float2*)Tp;
                float2 pi = make_float2(t0.x + t1.x + t2.x, t0.y + t1.y + t2.y);
                t0 = *(const float2*)(Tt+128);  t1 = *(const float2*)(Ts+128);  t2 = *(const float2*)(Tp+128);
                float2 po = make_float2(t0.x + t1.x + t2.x, t0.y + t1.y + t2.y);
                t0 = *(const float2*)(Tt+256);  t1 = *(const float2*)(Ts+256);  t2 = *(const float2*)(Tp+256);
                float2 pu = make_float2(t0.x + t1.x + t2.x, t0.y + t1.y + t2.y);
                t0 = *(const float2*)(Tt+384);  t1 = *(const float2*)(Ts+384);  t2 = *(const float2*)(Tp+384);
                float2 pf = make_float2(t0.x + t1.x + t2.x, t0.y + t1.y + t2.y);

                float2 cl = *(const float2*)&g_c[sgl[m] * 128 + c0];
                float2 cr = make_float2(0.f, 0.f);
                int gr = sgr[m];
                if (gr >= 0) cr = *(const float2*)&g_c[gr * 128 + c0];

                float cx = sigf(accI[mt][a]   + pi.x) * tanhf(accU[mt][a]   + pu.x)
                         + sigf(accFL[mt][a]  + pf.x) * cl.x
                         + sigf(accFR[mt][a]  + pf.x) * cr.x;
                float cy = sigf(accI[mt][a+1] + pi.y) * tanhf(accU[mt][a+1] + pu.y)
                         + sigf(accFL[mt][a+1] + pf.y) * cl.y
                         + sigf(accFR[mt][a+1] + pf.y) * cr.y;
                float hx = sigf(accO[mt][a]   + po.x) * tanhf(cx);
                float hy = sigf(accO[mt][a+1] + po.y) * tanhf(cy);

                int gg = sg[m];
                *(float2*)&g_c[gg * 128 + c0] = make_float2(cx, cy);
                *(float2*)&g_h[gg * 128 + c0] = make_float2(hx, hy);
                if (out) *(float2*)&out[(gg >> 10) * 128 + c0] = make_float2(hx, hy);
            }
    }
}

// ---------------------------------------------------------------------------
extern "C" void kernel_launch(void* const* d_in, const int* in_sizes, int n_in,
                              void* d_out, int out_size)
{
    const void* feats  = d_in[0];
    const float* emb   = (const float*)d_in[4];
    const float* sortt = (const float*)d_in[5];
    const float* pe    = (const float*)d_in[6];
    const float* Wiou  = (const float*)d_in[7];
    const float* Uiou  = (const float*)d_in[8];
    const float* biou  = (const float*)d_in[9];
    const float* Wf    = (const float*)d_in[10];
    const float* Uf    = (const float*)d_in[11];
    const float* bf    = (const float*)d_in[12];
    float* out = (float*)d_out;

    cudaFuncSetAttribute(k2_mma, cudaFuncAttributeMaxDynamicSharedMemorySize, SMEMSZ);

    kd_init<<<1, 1>>>();
    kd_detect<<<(3 * NN / 2 + 255) / 256, 256>>>((const int*)feats);
    k0_tables<<<761, 512>>>(emb, sortt, pe, Wiou, Wf, biou, bf);
    k0b_pack<<<256, 256>>>(Uiou, Uf);
    k1_leaves<<<16384, 256>>>(feats);

    // internal levels bottom-up: l=1 is node 511 (single child), then l=2..10
    k2_mma<<<NTREES / BM, 256, SMEMSZ>>>(feats, nullptr, 511, 1);
    for (int l = 2; l <= 10; l++) {
        int cnt = 1 << (10 - l);
        k2_mma<<<NTREES * cnt / BM, 256, SMEMSZ>>>(feats,
                                                   (l == 10) ? out : nullptr,
                                                   cnt - 1, cnt);
    }
}

// round 6
// speedup vs baseline: 1.9236x; 1.3667x over previous
#include <cuda_runtime.h>
#include <cstdint>

#define NTREES 256
#define NPT    1024
#define NN     (NTREES * NPT)          // 262144 nodes
#define VOCAB  5000
#define SORTV  64
#define NPOS   1024
#define TCOLS  512                     // 384 iou cols + 128 f cols
#define BM     64
#define PAD    132                     // padded row stride (conflict-free A frags)

// smem (uint32 tf32 bits): sHL[64*132], sHR, sHS
#define OFF_HL  0
#define OFF_HR  (64 * PAD)
#define OFF_HS  (2 * 64 * PAD)
#define SMEMSZ  (3 * 64 * PAD * 4)     // 101376 bytes

// Device-global scratch (allocation-free per harness rules)
__device__ float    g_h[NN * 128];     // 128 MB
__device__ float    g_c[NN * 128];     // 128 MB
__device__ float    g_Ttok[VOCAB * TCOLS];
__device__ float    g_Tsort[SORTV * TCOLS];
__device__ float    g_Tpos[NPOS * TCOLS];
__device__ unsigned g_Upk[64 * 16 * 64];  // tf32 B frags: [nf(64)][ks(16)][64 words]
__device__ int      g_is64;

__device__ __forceinline__ float sigf(float x) { return 1.0f / (1.0f + __expf(-x)); }
__device__ __forceinline__ uint32_t f2tf32(float f) {
    uint32_t r;
    asm("cvt.rna.tf32.f32 %0, %1;" : "=r"(r) : "f"(f));
    return r;
}
__device__ __forceinline__ uint4 cvt4(float4 v) {
    return make_uint4(f2tf32(v.x), f2tf32(v.y), f2tf32(v.z), f2tf32(v.w));
}

#define MMA(ACC, A0, A1, A2, A3, B)                                            \
    asm volatile(                                                              \
        "mma.sync.aligned.m16n8k8.row.col.f32.tf32.tf32.f32 "                  \
        "{%0,%1,%2,%3}, {%4,%5,%6,%7}, {%8,%9}, {%0,%1,%2,%3};\n"              \
        : "+f"(ACC[0]), "+f"(ACC[1]), "+f"(ACC[2]), "+f"(ACC[3])               \
        : "r"(A0), "r"(A1), "r"(A2), "r"(A3), "r"(B.x), "r"(B.y))

// Feature fetch for int32 or int64 feature buffers.
__device__ __forceinline__ int3 getfeat(const void* f, int g)
{
    if (g_is64) {
        const long long* p = (const long long*)f;
        return make_int3((int)p[3 * g], (int)p[3 * g + 1], (int)p[3 * g + 2]);
    }
    const int* p = (const int*)f;
    return make_int3(p[3 * g], p[3 * g + 1], p[3 * g + 2]);
}

// ---------------------------------------------------------------------------
// Dtype detection: one warp ballots 32 odd 32-bit words. int64 (<2^31) buffer
// has all odd words zero; int32 has random feature values there.
// ---------------------------------------------------------------------------
__global__ void kd_detect(const int* f)
{
    unsigned any = __ballot_sync(0xffffffffu, f[threadIdx.x * 2 + 1] != 0);
    if (threadIdx.x == 0) g_is64 = (any == 0u) ? 1 : 0;
}

// ---------------------------------------------------------------------------
// K0: projection tables (embedding @ W factored through the three tables).
// ---------------------------------------------------------------------------
__global__ void k0_tables(const float* __restrict__ emb,
                          const float* __restrict__ sortt,
                          const float* __restrict__ pe,
                          const float* __restrict__ Wiou,
                          const float* __restrict__ Wf,
                          const float* __restrict__ biou,
                          const float* __restrict__ bf)
{
    __shared__ float se[8][64];
    int b = blockIdx.x;
    int j = threadIdx.x;

    const float* src; int wbase; float* dst; bool addb;
    if (b < 625)      { int r0 = b * 8;         src = emb   + r0 * 64; wbase = 0;   dst = g_Ttok  + r0 * TCOLS; addb = false; }
    else if (b < 633) { int r0 = (b - 625) * 8; src = sortt + r0 * 64; wbase = 64;  dst = g_Tsort + r0 * TCOLS; addb = false; }
    else              { int r0 = (b - 633) * 8; src = pe    + r0 * 64; wbase = 128; dst = g_Tpos  + r0 * TCOLS; addb = true;  }

    se[j >> 6][j & 63] = src[j];
    __syncthreads();

    float acc[8];
#pragma unroll
    for (int r = 0; r < 8; r++) acc[r] = 0.0f;

    float bias = 0.0f;
    if (j < 384) {
#pragma unroll 8
        for (int k = 0; k < 64; k++) {
            float w = Wiou[(wbase + k) * 384 + j];
#pragma unroll
            for (int r = 0; r < 8; r++) acc[r] += se[r][k] * w;
        }
        if (addb) bias = biou[j];
    } else {
        int jj = j - 384;
#pragma unroll 8
        for (int k = 0; k < 64; k++) {
            float w = Wf[(wbase + k) * 128 + jj];
#pragma unroll
            for (int r = 0; r < 8; r++) acc[r] += se[r][k] * w;
        }
        if (addb) bias = bf[jj];
    }
#pragma unroll
    for (int r = 0; r < 8; r++) dst[r * TCOLS + j] = acc[r] + bias;
}

// ---------------------------------------------------------------------------
// K0b: pack U = [U_iou | U_f] into m16n8k8 B-fragment order (tf32 bits).
// ---------------------------------------------------------------------------
__global__ void k0b_pack(const float* __restrict__ Uiou, const float* __restrict__ Uf)
{
    int idx = blockIdx.x * 256 + threadIdx.x;   // 0..65535
    int f = idx >> 6, w = idx & 63;
    int nf = f >> 4, ks = f & 15;
    int lane = w >> 1, half = w & 1;
    int k = 8 * ks + (lane & 3) + 4 * half;
    int c = lane >> 2;
    float v = (nf < 48) ? Uiou[k * 384 + nf * 8 + c]
                        : Uf[k * 128 + (nf - 48) * 8 + c];
    g_Upk[idx] = f2tf32(v);
}

// ---------------------------------------------------------------------------
// K1: leaves, float4-vectorized. 256 threads = 8 leaves x 32 cols4.
// ---------------------------------------------------------------------------
__global__ void k1_leaves(const void* __restrict__ feats)
{
    int tid = threadIdx.x;
    int q   = tid & 31;                   // col group (4 floats)
    int L   = blockIdx.x * 8 + (tid >> 5);
    int t   = L >> 9;
    int i   = 512 + (L & 511);
    int g   = t * NPT + i;

    int3 ft = getfeat(feats, g);

    const float* Pt = g_Ttok  + ft.x * TCOLS + q * 4;
    const float* Ps = g_Tsort + ft.y * TCOLS + q * 4;
    const float* Pp = g_Tpos  + ft.z * TCOLS + q * 4;

    float4 a, b, d, pi, po, pu;
    a = *(const float4*)Pt;        b = *(const float4*)Ps;        d = *(const float4*)Pp;
    pi = make_float4(a.x+b.x+d.x, a.y+b.y+d.y, a.z+b.z+d.z, a.w+b.w+d.w);
    a = *(const float4*)(Pt+128);  b = *(const float4*)(Ps+128);  d = *(const float4*)(Pp+128);
    po = make_float4(a.x+b.x+d.x, a.y+b.y+d.y, a.z+b.z+d.z, a.w+b.w+d.w);
    a = *(const float4*)(Pt+256);  b = *(const float4*)(Ps+256);  d = *(const float4*)(Pp+256);
    pu = make_float4(a.x+b.x+d.x, a.y+b.y+d.y, a.z+b.z+d.z, a.w+b.w+d.w);

    float4 cv = make_float4(sigf(pi.x) * tanhf(pu.x), sigf(pi.y) * tanhf(pu.y),
                            sigf(pi.z) * tanhf(pu.z), sigf(pi.w) * tanhf(pu.w));
    float4 hv = make_float4(sigf(po.x) * tanhf(cv.x), sigf(po.y) * tanhf(cv.y),
                            sigf(po.z) * tanhf(cv.z), sigf(po.w) * tanhf(cv.w));
    *(float4*)&g_c[g * 128 + q * 4] = cv;
    *(float4*)&g_h[g * 128 + q * 4] = hv;
}

// ---------------------------------------------------------------------------
// K2: one internal level. BM=64 nodes/block, 256 threads, 2 blocks/SM.
// Warp item = 32 nodes x 8 cols; 5 gate accumulators in registers;
// epilogue entirely register-resident.
// ---------------------------------------------------------------------------
__global__ __launch_bounds__(256, 2) void k2_mma(
    const void* __restrict__ feats,
    float* __restrict__ out,
    int beg, int cnt)
{
    extern __shared__ unsigned smu[];
    unsigned* sHL = smu + OFF_HL;
    unsigned* sHR = smu + OFF_HR;
    unsigned* sHS = smu + OFF_HS;

    __shared__ int sg[BM], sgl[BM], sgr[BM], stok[BM], ssrt[BM], spos[BM];

    int tid  = threadIdx.x;
    int lane = tid & 31;
    int w    = tid >> 5;
    int g4   = lane >> 2, tg = lane & 3;

    if (tid < BM) {
        int m = blockIdx.x * BM + tid;
        int t = m / cnt, i = beg + m % cnt;
        int g = t * NPT + i;
        sg[tid]  = g;
        sgl[tid] = t * NPT + 2 * i + 1;
        int rr = 2 * i + 2;
        sgr[tid] = (rr < NPT) ? t * NPT + rr : -1;
        int3 ft = getfeat(feats, g);
        stok[tid] = ft.x;
        ssrt[tid] = ft.y;
        spos[tid] = ft.z;
    }
    __syncthreads();

    // Stage child h tiles as tf32 bits (hl, hr, hs=hl+hr)
#pragma unroll
    for (int r4 = 0; r4 < 8; r4++) {
        int idx = tid + r4 * 256;      // = m*32 + q
        int m = idx >> 5, q = idx & 31;
        float4 hl = *(const float4*)&g_h[sgl[m] * 128 + q * 4];
        float4 hr = make_float4(0.f, 0.f, 0.f, 0.f);
        int gr = sgr[m];
        if (gr >= 0) hr = *(const float4*)&g_h[gr * 128 + q * 4];
        *(uint4*)&sHL[m * PAD + q * 4] = cvt4(hl);
        *(uint4*)&sHR[m * PAD + q * 4] = cvt4(hr);
        *(uint4*)&sHS[m * PAD + q * 4] =
            cvt4(make_float4(hl.x + hr.x, hl.y + hr.y, hl.z + hr.z, hl.w + hr.w));
    }
    __syncthreads();

    // 4 items per warp: it = w + 8r;  mp = it>>4 (32-node half), cg = it&15 (8-col group)
#pragma unroll 1
    for (int r = 0; r < 4; r++) {
        int it = w + 8 * r;
        int mp = it >> 4, cg = it & 15;
        int mbase = mp * 32;

        float accI[2][4], accO[2][4], accU[2][4], accFL[2][4], accFR[2][4];
#pragma unroll
        for (int mt = 0; mt < 2; mt++)
#pragma unroll
            for (int e = 0; e < 4; e++) {
                accI[mt][e] = accO[mt][e] = accU[mt][e] = 0.0f;
                accFL[mt][e] = accFR[mt][e] = 0.0f;
            }

#pragma unroll 2
        for (int ks = 0; ks < 16; ks++) {
            uint2 bi = *(const uint2*)&g_Upk[((cg     ) * 16 + ks) * 64 + 2 * lane];
            uint2 bo = *(const uint2*)&g_Upk[((16 + cg) * 16 + ks) * 64 + 2 * lane];
            uint2 bu = *(const uint2*)&g_Upk[((32 + cg) * 16 + ks) * 64 + 2 * lane];
            uint2 bf = *(const uint2*)&g_Upk[((48 + cg) * 16 + ks) * 64 + 2 * lane];
#pragma unroll
            for (int mt = 0; mt < 2; mt++) {
                int rowoff = (mbase + mt * 16 + g4) * PAD + 8 * ks + tg;
                unsigned s0 = sHS[rowoff],           s1 = sHS[rowoff + 8 * PAD];
                unsigned s2 = sHS[rowoff + 4],       s3 = sHS[rowoff + 8 * PAD + 4];
                MMA(accI[mt], s0, s1, s2, s3, bi);
                MMA(accO[mt], s0, s1, s2, s3, bo);
                MMA(accU[mt], s0, s1, s2, s3, bu);
                unsigned l0 = sHL[rowoff],           l1 = sHL[rowoff + 8 * PAD];
                unsigned l2 = sHL[rowoff + 4],       l3 = sHL[rowoff + 8 * PAD + 4];
                MMA(accFL[mt], l0, l1, l2, l3, bf);
                unsigned r0 = sHR[rowoff],           r1 = sHR[rowoff + 8 * PAD];
                unsigned r2 = sHR[rowoff + 4],       r3 = sHR[rowoff + 8 * PAD + 4];
                MMA(accFR[mt], r0, r1, r2, r3, bf);
            }
        }

        // Register epilogue: rows m = mbase + mt*16 + rr*8 + g4, cols c0, c0+1.
        int c0 = cg * 8 + 2 * tg;
#pragma unroll
        for (int mt = 0; mt < 2; mt++)
#pragma unroll
            for (int rr = 0; rr < 2; rr++) {
                int m = mbase + mt * 16 + rr * 8 + g4;
                int a = rr * 2;
                const float* Tt = g_Ttok  + stok[m] * TCOLS + c0;
                const float* Ts = g_Tsort + ssrt[m] * TCOLS + c0;
                const float* Tp = g_Tpos  + spos[m] * TCOLS + c0;

                float2 t0, t1, t2;
                t0 = *(const float2*)Tt;        t1 = *(const float2*)Ts;        t2 = *(const float2*)Tp;
                float2 pi = make_float2(t0.x + t1.x + t2.x, t0.y + t1.y + t2.y);
                t0 = *(const float2*)(Tt+128);  t1 = *(const float2*)(Ts+128);  t2 = *(const float2*)(Tp+128);
                float2 po = make_float2(t0.x + t1.x + t2.x, t0.y + t1.y + t2.y);
                t0 = *(const float2*)(Tt+256);  t1 = *(const float2*)(Ts+256);  t2 = *(const float2*)(Tp+256);
                float2 pu = make_float2(t0.x + t1.x + t2.x, t0.y + t1.y + t2.y);
                t0 = *(const float2*)(Tt+384);  t1 = *(const float2*)(Ts+384);  t2 = *(const float2*)(Tp+384);
                float2 pf = make_float2(t0.x + t1.x + t2.x, t0.y + t1.y + t2.y);

                float2 cl = *(const float2*)&g_c[sgl[m] * 128 + c0];
                float2 cr = make_float2(0.f, 0.f);
                int gr = sgr[m];
                if (gr >= 0) cr = *(const float2*)&g_c[gr * 128 + c0];

                float cx = sigf(accI[mt][a]   + pi.x) * tanhf(accU[mt][a]   + pu.x)
                         + sigf(accFL[mt][a]  + pf.x) * cl.x
                         + sigf(accFR[mt][a]  + pf.x) * cr.x;
                float cy = sigf(accI[mt][a+1] + pi.y) * tanhf(accU[mt][a+1] + pu.y)
                         + sigf(accFL[mt][a+1] + pf.y) * cl.y
                         + sigf(accFR[mt][a+1] + pf.y) * cr.y;
                float hx = sigf(accO[mt][a]   + po.x) * tanhf(cx);
                float hy = sigf(accO[mt][a+1] + po.y) * tanhf(cy);

                int gg = sg[m];
                *(float2*)&g_c[gg * 128 + c0] = make_float2(cx, cy);
                *(float2*)&g_h[gg * 128 + c0] = make_float2(hx, hy);
                if (out) *(float2*)&out[(gg >> 10) * 128 + c0] = make_float2(hx, hy);
            }
    }
}

// ---------------------------------------------------------------------------
extern "C" void kernel_launch(void* const* d_in, const int* in_sizes, int n_in,
                              void* d_out, int out_size)
{
    const void* feats  = d_in[0];
    const float* emb   = (const float*)d_in[4];
    const float* sortt = (const float*)d_in[5];
    const float* pe    = (const float*)d_in[6];
    const float* Wiou  = (const float*)d_in[7];
    const float* Uiou  = (const float*)d_in[8];
    const float* biou  = (const float*)d_in[9];
    const float* Wf    = (const float*)d_in[10];
    const float* Uf    = (const float*)d_in[11];
    const float* bf    = (const float*)d_in[12];
    float* out = (float*)d_out;

    cudaFuncSetAttribute(k2_mma, cudaFuncAttributeMaxDynamicSharedMemorySize, SMEMSZ);

    kd_detect<<<1, 32>>>((const int*)feats);
    k0_tables<<<761, 512>>>(emb, sortt, pe, Wiou, Wf, biou, bf);
    k0b_pack<<<256, 256>>>(Uiou, Uf);
    k1_leaves<<<16384, 256>>>(feats);

    // internal levels bottom-up: l=1 is node 511 (single child), then l=2..10
    k2_mma<<<NTREES / BM, 256, SMEMSZ>>>(feats, nullptr, 511, 1);
    for (int l = 2; l <= 10; l++) {
        int cnt = 1 << (10 - l);
        k2_mma<<<NTREES * cnt / BM, 256, SMEMSZ>>>(feats,
                                                   (l == 10) ? out : nullptr,
                                                   cnt - 1, cnt);
    }
}

// round 7
// speedup vs baseline: 2.2478x; 1.1685x over previous
#include <cuda_runtime.h>
#include <cstdint>

#define NTREES 256
#define NPT    1024
#define NN     (NTREES * NPT)          // 262144 nodes
#define VOCAB  5000
#define SORTV  64
#define NPOS   1024
#define TCOLS  512                     // 384 iou cols + 128 f cols
#define BM     64
#define PAD    132                     // padded row stride (conflict-free A frags)

// smem (uint32 tf32 bits): sHL[64*132], sHR, sHS
#define OFF_HL  0
#define OFF_HR  (64 * PAD)
#define OFF_HS  (2 * 64 * PAD)
#define SMEMSZ  (3 * 64 * PAD * 4)     // 101376 bytes

// Device-global scratch (allocation-free per harness rules)
__device__ float    g_h[NN * 128];     // 128 MB
__device__ float    g_c[NN * 128];     // 128 MB
__device__ float    g_Ttok[VOCAB * TCOLS];
__device__ float    g_Tsort[SORTV * TCOLS];
__device__ float    g_Tpos[NPOS * TCOLS];
__device__ unsigned g_Upk[64 * 16 * 64];  // tf32 B frags: [nf(64)][ks(16)][64 words]
__device__ int      g_is64;

__device__ __forceinline__ float sigf(float x) { return 1.0f / (1.0f + __expf(-x)); }
__device__ __forceinline__ uint32_t f2tf32(float f) {
    uint32_t r;
    asm("cvt.rna.tf32.f32 %0, %1;" : "=r"(r) : "f"(f));
    return r;
}
__device__ __forceinline__ uint4 cvt4(float4 v) {
    return make_uint4(f2tf32(v.x), f2tf32(v.y), f2tf32(v.z), f2tf32(v.w));
}

#define MMA(ACC, A0, A1, A2, A3, B)                                            \
    asm volatile(                                                              \
        "mma.sync.aligned.m16n8k8.row.col.f32.tf32.tf32.f32 "                  \
        "{%0,%1,%2,%3}, {%4,%5,%6,%7}, {%8,%9}, {%0,%1,%2,%3};\n"              \
        : "+f"(ACC[0]), "+f"(ACC[1]), "+f"(ACC[2]), "+f"(ACC[3])               \
        : "r"(A0), "r"(A1), "r"(A2), "r"(A3), "r"(B.x), "r"(B.y))

// Feature fetch for int32 or int64 feature buffers.
__device__ __forceinline__ int3 getfeat(const void* f, int g)
{
    if (g_is64) {
        const long long* p = (const long long*)f;
        return make_int3((int)p[3 * g], (int)p[3 * g + 1], (int)p[3 * g + 2]);
    }
    const int* p = (const int*)f;
    return make_int3(p[3 * g], p[3 * g + 1], p[3 * g + 2]);
}

// ---------------------------------------------------------------------------
// Dtype detection: one warp ballots 32 odd 32-bit words. int64 (<2^31) buffer
// has all odd words zero; int32 has random feature values there.
// ---------------------------------------------------------------------------
__global__ void kd_detect(const int* f)
{
    unsigned any = __ballot_sync(0xffffffffu, f[threadIdx.x * 2 + 1] != 0);
    if (threadIdx.x == 0) g_is64 = (any == 0u) ? 1 : 0;
}

// ---------------------------------------------------------------------------
// K0: projection tables (embedding @ W factored through the three tables).
// ---------------------------------------------------------------------------
__global__ void k0_tables(const float* __restrict__ emb,
                          const float* __restrict__ sortt,
                          const float* __restrict__ pe,
                          const float* __restrict__ Wiou,
                          const float* __restrict__ Wf,
                          const float* __restrict__ biou,
                          const float* __restrict__ bf)
{
    __shared__ float se[8][64];
    int b = blockIdx.x;
    int j = threadIdx.x;

    const float* src; int wbase; float* dst; bool addb;
    if (b < 625)      { int r0 = b * 8;         src = emb   + r0 * 64; wbase = 0;   dst = g_Ttok  + r0 * TCOLS; addb = false; }
    else if (b < 633) { int r0 = (b - 625) * 8; src = sortt + r0 * 64; wbase = 64;  dst = g_Tsort + r0 * TCOLS; addb = false; }
    else              { int r0 = (b - 633) * 8; src = pe    + r0 * 64; wbase = 128; dst = g_Tpos  + r0 * TCOLS; addb = true;  }

    se[j >> 6][j & 63] = src[j];
    __syncthreads();

    float acc[8];
#pragma unroll
    for (int r = 0; r < 8; r++) acc[r] = 0.0f;

    float bias = 0.0f;
    if (j < 384) {
#pragma unroll 8
        for (int k = 0; k < 64; k++) {
            float w = Wiou[(wbase + k) * 384 + j];
#pragma unroll
            for (int r = 0; r < 8; r++) acc[r] += se[r][k] * w;
        }
        if (addb) bias = biou[j];
    } else {
        int jj = j - 384;
#pragma unroll 8
        for (int k = 0; k < 64; k++) {
            float w = Wf[(wbase + k) * 128 + jj];
#pragma unroll
            for (int r = 0; r < 8; r++) acc[r] += se[r][k] * w;
        }
        if (addb) bias = bf[jj];
    }
#pragma unroll
    for (int r = 0; r < 8; r++) dst[r * TCOLS + j] = acc[r] + bias;
}

// ---------------------------------------------------------------------------
// K0b: pack U = [U_iou | U_f] into m16n8k8 B-fragment order (tf32 bits).
// ---------------------------------------------------------------------------
__global__ void k0b_pack(const float* __restrict__ Uiou, const float* __restrict__ Uf)
{
    int idx = blockIdx.x * 256 + threadIdx.x;   // 0..65535
    int f = idx >> 6, w = idx & 63;
    int nf = f >> 4, ks = f & 15;
    int lane = w >> 1, half = w & 1;
    int k = 8 * ks + (lane & 3) + 4 * half;
    int c = lane >> 2;
    float v = (nf < 48) ? Uiou[k * 384 + nf * 8 + c]
                        : Uf[k * 128 + (nf - 48) * 8 + c];
    g_Upk[idx] = f2tf32(v);
}

// ---------------------------------------------------------------------------
// K1: leaves, float4-vectorized. 256 threads = 8 leaves x 32 cols4.
// ---------------------------------------------------------------------------
__global__ void k1_leaves(const void* __restrict__ feats)
{
    int tid = threadIdx.x;
    int q   = tid & 31;                   // col group (4 floats)
    int L   = blockIdx.x * 8 + (tid >> 5);
    int t   = L >> 9;
    int i   = 512 + (L & 511);
    int g   = t * NPT + i;

    int3 ft = getfeat(feats, g);

    const float* Pt = g_Ttok  + ft.x * TCOLS + q * 4;
    const float* Ps = g_Tsort + ft.y * TCOLS + q * 4;
    const float* Pp = g_Tpos  + ft.z * TCOLS + q * 4;

    float4 a, b, d, pi, po, pu;
    a = *(const float4*)Pt;        b = *(const float4*)Ps;        d = *(const float4*)Pp;
    pi = make_float4(a.x+b.x+d.x, a.y+b.y+d.y, a.z+b.z+d.z, a.w+b.w+d.w);
    a = *(const float4*)(Pt+128);  b = *(const float4*)(Ps+128);  d = *(const float4*)(Pp+128);
    po = make_float4(a.x+b.x+d.x, a.y+b.y+d.y, a.z+b.z+d.z, a.w+b.w+d.w);
    a = *(const float4*)(Pt+256);  b = *(const float4*)(Ps+256);  d = *(const float4*)(Pp+256);
    pu = make_float4(a.x+b.x+d.x, a.y+b.y+d.y, a.z+b.z+d.z, a.w+b.w+d.w);

    float4 cv = make_float4(sigf(pi.x) * tanhf(pu.x), sigf(pi.y) * tanhf(pu.y),
                            sigf(pi.z) * tanhf(pu.z), sigf(pi.w) * tanhf(pu.w));
    float4 hv = make_float4(sigf(po.x) * tanhf(cv.x), sigf(po.y) * tanhf(cv.y),
                            sigf(po.z) * tanhf(cv.z), sigf(po.w) * tanhf(cv.w));
    *(float4*)&g_c[g * 128 + q * 4] = cv;
    *(float4*)&g_h[g * 128 + q * 4] = hv;
}

// ---------------------------------------------------------------------------
// K2: persistent per-tree kernel. Block = one tree; loops levels 1..10
// bottom-up, chunking each level into <=64-node tiles. All 256 blocks are
// resident in one wave (2 blocks/SM), so child h/c stay L2-hot and there
// are no launch/tail overheads between levels.
// ---------------------------------------------------------------------------
__global__ __launch_bounds__(256, 2) void k2_tree(
    const void* __restrict__ feats,
    float* __restrict__ out)
{
    extern __shared__ unsigned smu[];
    unsigned* sHL = smu + OFF_HL;
    unsigned* sHR = smu + OFF_HR;
    unsigned* sHS = smu + OFF_HS;

    __shared__ int sg[BM], sgl[BM], sgr[BM], stok[BM], ssrt[BM], spos[BM];

    int tid  = threadIdx.x;
    int lane = tid & 31;
    int w    = tid >> 5;
    int g4   = lane >> 2, tg = lane & 3;
    int tb   = blockIdx.x * NPT;       // tree base node

    for (int l = 1; l <= 10; l++) {
        int cnt = (l == 1) ? 1 : (1 << (10 - l));
        int beg = (l == 1) ? 511 : cnt - 1;

        for (int ch = 0; ch < cnt; ch += BM) {
            int n = cnt - ch; if (n > BM) n = BM;   // valid rows this chunk

            __syncthreads();   // protect smem/index arrays from prior chunk readers
            if (tid < BM) {
                int m = (tid < n) ? tid : 0;        // clamp padding rows to a valid node
                int i = beg + ch + m;
                int g = tb + i;
                sg[tid]  = g;
                sgl[tid] = tb + 2 * i + 1;
                int rr2 = 2 * i + 2;
                sgr[tid] = (rr2 < NPT) ? tb + rr2 : -1;   // node 511: single child
                int3 ft = getfeat(feats, g);
                stok[tid] = ft.x;
                ssrt[tid] = ft.y;
                spos[tid] = ft.z;
            }
            __syncthreads();

            // Stage child h tiles as tf32 bits (hl, hr, hs=hl+hr)
#pragma unroll
            for (int r4 = 0; r4 < 8; r4++) {
                int idx = tid + r4 * 256;      // = m*32 + q
                int m = idx >> 5, q = idx & 31;
                float4 hl = *(const float4*)&g_h[sgl[m] * 128 + q * 4];
                float4 hr = make_float4(0.f, 0.f, 0.f, 0.f);
                int gr = sgr[m];
                if (gr >= 0) hr = *(const float4*)&g_h[gr * 128 + q * 4];
                *(uint4*)&sHL[m * PAD + q * 4] = cvt4(hl);
                *(uint4*)&sHR[m * PAD + q * 4] = cvt4(hr);
                *(uint4*)&sHS[m * PAD + q * 4] =
                    cvt4(make_float4(hl.x + hr.x, hl.y + hr.y, hl.z + hr.z, hl.w + hr.w));
            }
            __syncthreads();

            // 4 items per warp: it = w + 8r; mp = it>>4 (32-node half), cg = it&15
#pragma unroll 1
            for (int r = 0; r < 4; r++) {
                int it = w + 8 * r;
                int mp = it >> 4, cg = it & 15;
                int mbase = mp * 32;
                if (mbase >= n) continue;          // skip empty half on small levels

                float accI[2][4], accO[2][4], accU[2][4], accFL[2][4], accFR[2][4];
#pragma unroll
                for (int mt = 0; mt < 2; mt++)
#pragma unroll
                    for (int e = 0; e < 4; e++) {
                        accI[mt][e] = accO[mt][e] = accU[mt][e] = 0.0f;
                        accFL[mt][e] = accFR[mt][e] = 0.0f;
                    }

#pragma unroll 2
                for (int ks = 0; ks < 16; ks++) {
                    uint2 bi = *(const uint2*)&g_Upk[((cg     ) * 16 + ks) * 64 + 2 * lane];
                    uint2 bo = *(const uint2*)&g_Upk[((16 + cg) * 16 + ks) * 64 + 2 * lane];
                    uint2 bu = *(const uint2*)&g_Upk[((32 + cg) * 16 + ks) * 64 + 2 * lane];
                    uint2 bf = *(const uint2*)&g_Upk[((48 + cg) * 16 + ks) * 64 + 2 * lane];
#pragma unroll
                    for (int mt = 0; mt < 2; mt++) {
                        int rowoff = (mbase + mt * 16 + g4) * PAD + 8 * ks + tg;
                        unsigned s0 = sHS[rowoff],     s1 = sHS[rowoff + 8 * PAD];
                        unsigned s2 = sHS[rowoff + 4], s3 = sHS[rowoff + 8 * PAD + 4];
                        MMA(accI[mt], s0, s1, s2, s3, bi);
                        MMA(accO[mt], s0, s1, s2, s3, bo);
                        MMA(accU[mt], s0, s1, s2, s3, bu);
                        unsigned l0 = sHL[rowoff],     l1 = sHL[rowoff + 8 * PAD];
                        unsigned l2 = sHL[rowoff + 4], l3 = sHL[rowoff + 8 * PAD + 4];
                        MMA(accFL[mt], l0, l1, l2, l3, bf);
                        unsigned r0 = sHR[rowoff],     r1 = sHR[rowoff + 8 * PAD];
                        unsigned r2 = sHR[rowoff + 4], r3 = sHR[rowoff + 8 * PAD + 4];
                        MMA(accFR[mt], r0, r1, r2, r3, bf);
                    }
                }

                // Register epilogue: rows m = mbase + mt*16 + rr*8 + g4, cols c0,c0+1.
                int c0 = cg * 8 + 2 * tg;
#pragma unroll
                for (int mt = 0; mt < 2; mt++)
#pragma unroll
                    for (int rr = 0; rr < 2; rr++) {
                        int m = mbase + mt * 16 + rr * 8 + g4;
                        if (m >= n) continue;
                        int a = rr * 2;
                        const float* Tt = g_Ttok  + stok[m] * TCOLS + c0;
                        const float* Ts = g_Tsort + ssrt[m] * TCOLS + c0;
                        const float* Tp = g_Tpos  + spos[m] * TCOLS + c0;

                        float2 t0, t1, t2;
                        t0 = *(const float2*)Tt;        t1 = *(const float2*)Ts;        t2 = *(const float2*)Tp;
                        float2 pi = make_float2(t0.x + t1.x + t2.x, t0.y + t1.y + t2.y);
                        t0 = *(const float2*)(Tt+128);  t1 = *(const float2*)(Ts+128);  t2 = *(const float2*)(Tp+128);
                        float2 po = make_float2(t0.x + t1.x + t2.x, t0.y + t1.y + t2.y);
                        t0 = *(const float2*)(Tt+256);  t1 = *(const float2*)(Ts+256);  t2 = *(const float2*)(Tp+256);
                        float2 pu = make_float2(t0.x + t1.x + t2.x, t0.y + t1.y + t2.y);
                        t0 = *(const float2*)(Tt+384);  t1 = *(const float2*)(Ts+384);  t2 = *(const float2*)(Tp+384);
                        float2 pf = make_float2(t0.x + t1.x + t2.x, t0.y + t1.y + t2.y);

                        float2 cl = *(const float2*)&g_c[sgl[m] * 128 + c0];
                        float2 cr = make_float2(0.f, 0.f);
                        int gr = sgr[m];
                        if (gr >= 0) cr = *(const float2*)&g_c[gr * 128 + c0];

                        float cx = sigf(accI[mt][a]   + pi.x) * tanhf(accU[mt][a]   + pu.x)
                                 + sigf(accFL[mt][a]  + pf.x) * cl.x
                                 + sigf(accFR[mt][a]  + pf.x) * cr.x;
                        float cy = sigf(accI[mt][a+1] + pi.y) * tanhf(accU[mt][a+1] + pu.y)
                                 + sigf(accFL[mt][a+1] + pf.y) * cl.y
                                 + sigf(accFR[mt][a+1] + pf.y) * cr.y;
                        float hx = sigf(accO[mt][a]   + po.x) * tanhf(cx);
                        float hy = sigf(accO[mt][a+1] + po.y) * tanhf(cy);

                        int gg = sg[m];
                        *(float2*)&g_c[gg * 128 + c0] = make_float2(cx, cy);
                        *(float2*)&g_h[gg * 128 + c0] = make_float2(hx, hy);
                        if (l == 10)
                            *(float2*)&out[(gg >> 10) * 128 + c0] = make_float2(hx, hy);
                    }
            }
        }
    }
}

// ---------------------------------------------------------------------------
extern "C" void kernel_launch(void* const* d_in, const int* in_sizes, int n_in,
                              void* d_out, int out_size)
{
    const void* feats  = d_in[0];
    const float* emb   = (const float*)d_in[4];
    const float* sortt = (const float*)d_in[5];
    const float* pe    = (const float*)d_in[6];
    const float* Wiou  = (const float*)d_in[7];
    const float* Uiou  = (const float*)d_in[8];
    const float* biou  = (const float*)d_in[9];
    const float* Wf    = (const float*)d_in[10];
    const float* Uf    = (const float*)d_in[11];
    const float* bf    = (const float*)d_in[12];
    float* out = (float*)d_out;

    cudaFuncSetAttribute(k2_tree, cudaFuncAttributeMaxDynamicSharedMemorySize, SMEMSZ);

    kd_detect<<<1, 32>>>((const int*)feats);
    k0_tables<<<761, 512>>>(emb, sortt, pe, Wiou, Wf, biou, bf);
    k0b_pack<<<256, 256>>>(Uiou, Uf);
    k1_leaves<<<16384, 256>>>(feats);

    // All internal levels in one persistent launch: block = tree.
    k2_tree<<<NTREES, 256, SMEMSZ>>>(feats, out);
}

// round 9
// speedup vs baseline: 2.8750x; 1.2790x over previous
#include <cuda_runtime.h>
#include <cstdint>

#define NTREES 256
#define NPT    1024
#define NN     (NTREES * NPT)          // 262144 nodes
#define VOCAB  5000
#define SORTV  64
#define NPOS   1024
#define TCOLS  512                     // 384 iou cols + 128 f cols
#define BM     64
#define PAD    132                     // padded row stride (conflict-free A frags)

// smem (uint32 tf32 bits): sHL[64*132], sHR[64*132]
#define SMEMSZ  (2 * 64 * PAD * 4)     // 67584 bytes

// Device-global scratch (allocation-free per harness rules)
__device__ float    g_h[NN * 128];     // 128 MB
__device__ float    g_c[NN * 128];     // 128 MB
__device__ float    g_Ttok[VOCAB * TCOLS];
__device__ float    g_Tsort[SORTV * TCOLS];
__device__ float    g_Tpos[NPOS * TCOLS];
__device__ unsigned g_Upk[64 * 16 * 64];  // tf32 B frags: [nf(64)][ks(16)][64 words]
__device__ int      g_is64;

__device__ __forceinline__ float tanha(float x) {
    float r;
    asm("tanh.approx.f32 %0, %1;" : "=f"(r) : "f"(x));
    return r;
}
__device__ __forceinline__ float sigf(float x) {
    return fmaf(0.5f, tanha(0.5f * x), 0.5f);
}
__device__ __forceinline__ uint32_t f2tf32(float f) {
    uint32_t r;
    asm("cvt.rna.tf32.f32 %0, %1;" : "=r"(r) : "f"(f));
    return r;
}
__device__ __forceinline__ uint4 cvt4(float4 v) {
    return make_uint4(f2tf32(v.x), f2tf32(v.y), f2tf32(v.z), f2tf32(v.w));
}
// add two tf32-bit values (result has a few extra mantissa bits; mma truncates)
__device__ __forceinline__ unsigned addtf(unsigned a, unsigned b) {
    return __float_as_uint(__uint_as_float(a) + __uint_as_float(b));
}

#define MMA(ACC, A0, A1, A2, A3, B)                                            \
    asm volatile(                                                              \
        "mma.sync.aligned.m16n8k8.row.col.f32.tf32.tf32.f32 "                  \
        "{%0,%1,%2,%3}, {%4,%5,%6,%7}, {%8,%9}, {%0,%1,%2,%3};\n"              \
        : "+f"(ACC[0]), "+f"(ACC[1]), "+f"(ACC[2]), "+f"(ACC[3])               \
        : "r"(A0), "r"(A1), "r"(A2), "r"(A3), "r"(B.x), "r"(B.y))

// Feature fetch for int32 or int64 feature buffers.
__device__ __forceinline__ int3 getfeat(const void* f, int g)
{
    if (g_is64) {
        const long long* p = (const long long*)f;
        return make_int3((int)p[3 * g], (int)p[3 * g + 1], (int)p[3 * g + 2]);
    }
    const int* p = (const int*)f;
    return make_int3(p[3 * g], p[3 * g + 1], p[3 * g + 2]);
}

// ---------------------------------------------------------------------------
// Dtype detection: one warp ballots 32 odd 32-bit words.
// ---------------------------------------------------------------------------
__global__ void kd_detect(const int* f)
{
    unsigned any = __ballot_sync(0xffffffffu, f[threadIdx.x * 2 + 1] != 0);
    if (threadIdx.x == 0) g_is64 = (any == 0u) ? 1 : 0;
}

// ---------------------------------------------------------------------------
// K0: projection tables (embedding @ W factored through the three tables).
// ---------------------------------------------------------------------------
__global__ void k0_tables(const float* __restrict__ emb,
                          const float* __restrict__ sortt,
                          const float* __restrict__ pe,
                          const float* __restrict__ Wiou,
                          const float* __restrict__ Wf,
                          const float* __restrict__ biou,
                          const float* __restrict__ bf)
{
    __shared__ float se[8][64];
    int b = blockIdx.x;
    int j = threadIdx.x;

    const float* src; int wbase; float* dst; bool addb;
    if (b < 625)      { int r0 = b * 8;         src = emb   + r0 * 64; wbase = 0;   dst = g_Ttok  + r0 * TCOLS; addb = false; }
    else if (b < 633) { int r0 = (b - 625) * 8; src = sortt + r0 * 64; wbase = 64;  dst = g_Tsort + r0 * TCOLS; addb = false; }
    else              { int r0 = (b - 633) * 8; src = pe    + r0 * 64; wbase = 128; dst = g_Tpos  + r0 * TCOLS; addb = true;  }

    se[j >> 6][j & 63] = src[j];
    __syncthreads();

    float acc[8];
#pragma unroll
    for (int r = 0; r < 8; r++) acc[r] = 0.0f;

    float bias = 0.0f;
    if (j < 384) {
#pragma unroll 8
        for (int k = 0; k < 64; k++) {
            float w = Wiou[(wbase + k) * 384 + j];
#pragma unroll
            for (int r = 0; r < 8; r++) acc[r] += se[r][k] * w;
        }
        if (addb) bias = biou[j];
    } else {
        int jj = j - 384;
#pragma unroll 8
        for (int k = 0; k < 64; k++) {
            float w = Wf[(wbase + k) * 128 + jj];
#pragma unroll
            for (int r = 0; r < 8; r++) acc[r] += se[r][k] * w;
        }
        if (addb) bias = bf[jj];
    }
#pragma unroll
    for (int r = 0; r < 8; r++) dst[r * TCOLS + j] = acc[r] + bias;
}

// ---------------------------------------------------------------------------
// K0b: pack U = [U_iou | U_f] into m16n8k8 B-fragment order (tf32 bits).
// ---------------------------------------------------------------------------
__global__ void k0b_pack(const float* __restrict__ Uiou, const float* __restrict__ Uf)
{
    int idx = blockIdx.x * 256 + threadIdx.x;   // 0..65535
    int f = idx >> 6, w = idx & 63;
    int nf = f >> 4, ks = f & 15;
    int lane = w >> 1, half = w & 1;
    int k = 8 * ks + (lane & 3) + 4 * half;
    int c = lane >> 2;
    float v = (nf < 48) ? Uiou[k * 384 + nf * 8 + c]
                        : Uf[k * 128 + (nf - 48) * 8 + c];
    g_Upk[idx] = f2tf32(v);
}

// ---------------------------------------------------------------------------
// K1: leaves, float4-vectorized. 256 threads = 8 leaves x 32 cols4.
// ---------------------------------------------------------------------------
__global__ void k1_leaves(const void* __restrict__ feats)
{
    int tid = threadIdx.x;
    int q   = tid & 31;
    int L   = blockIdx.x * 8 + (tid >> 5);
    int t   = L >> 9;
    int i   = 512 + (L & 511);
    int g   = t * NPT + i;

    int3 ft = getfeat(feats, g);

    const float* Pt = g_Ttok  + ft.x * TCOLS + q * 4;
    const float* Ps = g_Tsort + ft.y * TCOLS + q * 4;
    const float* Pp = g_Tpos  + ft.z * TCOLS + q * 4;

    float4 a, b, d, pi, po, pu;
    a = *(const float4*)Pt;        b = *(const float4*)Ps;        d = *(const float4*)Pp;
    pi = make_float4(a.x+b.x+d.x, a.y+b.y+d.y, a.z+b.z+d.z, a.w+b.w+d.w);
    a = *(const float4*)(Pt+128);  b = *(const float4*)(Ps+128);  d = *(const float4*)(Pp+128);
    po = make_float4(a.x+b.x+d.x, a.y+b.y+d.y, a.z+b.z+d.z, a.w+b.w+d.w);
    a = *(const float4*)(Pt+256);  b = *(const float4*)(Ps+256);  d = *(const float4*)(Pp+256);
    pu = make_float4(a.x+b.x+d.x, a.y+b.y+d.y, a.z+b.z+d.z, a.w+b.w+d.w);

    float4 cv = make_float4(sigf(pi.x) * tanha(pu.x), sigf(pi.y) * tanha(pu.y),
                            sigf(pi.z) * tanha(pu.z), sigf(pi.w) * tanha(pu.w));
    float4 hv = make_float4(sigf(po.x) * tanha(cv.x), sigf(po.y) * tanha(cv.y),
                            sigf(po.z) * tanha(cv.z), sigf(po.w) * tanha(cv.w));
    *(float4*)&g_c[g * 128 + q * 4] = cv;
    *(float4*)&g_h[g * 128 + q * 4] = hv;
}

// ---------------------------------------------------------------------------
// K2: persistent per-tree kernel. Block = one tree; levels 1..10 bottom-up,
// <=64-node chunks. Inner loop: one cg (8 cols) per pass, 4 m-tiles (64 rows)
// share each B fragment load; hs formed in registers from hl+hr.
// ---------------------------------------------------------------------------
__global__ __launch_bounds__(256, 2) void k2_tree(
    const void* __restrict__ feats,
    float* __restrict__ out)
{
    extern __shared__ unsigned smu[];
    unsigned* sHL = smu;
    unsigned* sHR = smu + 64 * PAD;

    __shared__ int sg[BM], sgl[BM], sgr[BM], stok[BM], ssrt[BM], spos[BM];

    int tid  = threadIdx.x;
    int lane = tid & 31;
    int w    = tid >> 5;
    int g4   = lane >> 2, tg = lane & 3;
    int tb   = blockIdx.x * NPT;       // tree base node

    for (int l = 1; l <= 10; l++) {
        int cnt = (l == 1) ? 1 : (1 << (10 - l));
        int beg = (l == 1) ? 511 : cnt - 1;

        for (int ch = 0; ch < cnt; ch += BM) {
            int n = cnt - ch; if (n > BM) n = BM;   // valid rows this chunk

            __syncthreads();   // protect smem/index arrays from prior chunk readers
            if (tid < BM) {
                int m = (tid < n) ? tid : 0;        // clamp padding rows
                int i = beg + ch + m;
                int g = tb + i;
                sg[tid]  = g;
                sgl[tid] = tb + 2 * i + 1;
                int rr2 = 2 * i + 2;
                sgr[tid] = (rr2 < NPT) ? tb + rr2 : -1;   // node 511: single child
                int3 ft = getfeat(feats, g);
                stok[tid] = ft.x;
                ssrt[tid] = ft.y;
                spos[tid] = ft.z;
            }
            __syncthreads();

            // Stage child h tiles as tf32 bits (hl, hr)
#pragma unroll
            for (int r4 = 0; r4 < 8; r4++) {
                int idx = tid + r4 * 256;      // = m*32 + q
                int m = idx >> 5, q = idx & 31;
                float4 hl = *(const float4*)&g_h[sgl[m] * 128 + q * 4];
                float4 hr = make_float4(0.f, 0.f, 0.f, 0.f);
                int gr = sgr[m];
                if (gr >= 0) hr = *(const float4*)&g_h[gr * 128 + q * 4];
                *(uint4*)&sHL[m * PAD + q * 4] = cvt4(hl);
                *(uint4*)&sHR[m * PAD + q * 4] = cvt4(hr);
            }
            __syncthreads();

            // Two col-groups per warp; 4 m-tiles (64 rows) share each B load.
#pragma unroll 1
            for (int cgi = 0; cgi < 2; cgi++) {
                int cg = w + 8 * cgi;          // 0..15

                float accI[4][4], accO[4][4], accU[4][4], accFL[4][4], accFR[4][4];
#pragma unroll
                for (int mt = 0; mt < 4; mt++)
#pragma unroll
                    for (int e = 0; e < 4; e++) {
                        accI[mt][e] = accO[mt][e] = accU[mt][e] = 0.0f;
                        accFL[mt][e] = accFR[mt][e] = 0.0f;
                    }

#pragma unroll 1
                for (int ks = 0; ks < 16; ks++) {
                    uint2 bi = *(const uint2*)&g_Upk[((cg     ) * 16 + ks) * 64 + 2 * lane];
                    uint2 bo = *(const uint2*)&g_Upk[((16 + cg) * 16 + ks) * 64 + 2 * lane];
                    uint2 bu = *(const uint2*)&g_Upk[((32 + cg) * 16 + ks) * 64 + 2 * lane];
                    uint2 bf = *(const uint2*)&g_Upk[((48 + cg) * 16 + ks) * 64 + 2 * lane];
#pragma unroll
                    for (int mt = 0; mt < 4; mt++) {
                        if (mt * 16 < n) {
                            int rowoff = (mt * 16 + g4) * PAD + 8 * ks + tg;
                            unsigned l0 = sHL[rowoff],     l1 = sHL[rowoff + 8 * PAD];
                            unsigned l2 = sHL[rowoff + 4], l3 = sHL[rowoff + 8 * PAD + 4];
                            unsigned r0 = sHR[rowoff],     r1 = sHR[rowoff + 8 * PAD];
                            unsigned r2 = sHR[rowoff + 4], r3 = sHR[rowoff + 8 * PAD + 4];
                            unsigned s0 = addtf(l0, r0),   s1 = addtf(l1, r1);
                            unsigned s2 = addtf(l2, r2),   s3 = addtf(l3, r3);
                            MMA(accI[mt], s0, s1, s2, s3, bi);
                            MMA(accO[mt], s0, s1, s2, s3, bo);
                            MMA(accU[mt], s0, s1, s2, s3, bu);
                            MMA(accFL[mt], l0, l1, l2, l3, bf);
                            MMA(accFR[mt], r0, r1, r2, r3, bf);
                        }
                    }
                }

                // Register epilogue: rows m = mt*16 + rr*8 + g4, cols c0, c0+1.
                int c0 = cg * 8 + 2 * tg;
#pragma unroll
                for (int mt = 0; mt < 4; mt++)
#pragma unroll
                    for (int rr = 0; rr < 2; rr++) {
                        int m = mt * 16 + rr * 8 + g4;
                        if (m >= n) continue;
                        int a = rr * 2;
                        const float* Tt = g_Ttok  + stok[m] * TCOLS + c0;
                        const float* Ts = g_Tsort + ssrt[m] * TCOLS + c0;
                        const float* Tp = g_Tpos  + spos[m] * TCOLS + c0;

                        float2 t0, t1, t2;
                        t0 = *(const float2*)Tt;        t1 = *(const float2*)Ts;        t2 = *(const float2*)Tp;
                        float2 pi = make_float2(t0.x + t1.x + t2.x, t0.y + t1.y + t2.y);
                        t0 = *(const float2*)(Tt+128);  t1 = *(const float2*)(Ts+128);  t2 = *(const float2*)(Tp+128);
                        float2 po = make_float2(t0.x + t1.x + t2.x, t0.y + t1.y + t2.y);
                        t0 = *(const float2*)(Tt+256);  t1 = *(const float2*)(Ts+256);  t2 = *(const float2*)(Tp+256);
                        float2 pu = make_float2(t0.x + t1.x + t2.x, t0.y + t1.y + t2.y);
                        t0 = *(const float2*)(Tt+384);  t1 = *(const float2*)(Ts+384);  t2 = *(const float2*)(Tp+384);
                        float2 pf = make_float2(t0.x + t1.x + t2.x, t0.y + t1.y + t2.y);

                        float2 cl = *(const float2*)&g_c[sgl[m] * 128 + c0];
                        float2 cr = make_float2(0.f, 0.f);
                        int gr = sgr[m];
                        if (gr >= 0) cr = *(const float2*)&g_c[gr * 128 + c0];

                        float cx = sigf(accI[mt][a]   + pi.x) * tanha(accU[mt][a]   + pu.x)
                                 + sigf(accFL[mt][a]  + pf.x) * cl.x
                                 + sigf(accFR[mt][a]  + pf.x) * cr.x;
                        float cy = sigf(accI[mt][a+1] + pi.y) * tanha(accU[mt][a+1] + pu.y)
                                 + sigf(accFL[mt][a+1] + pf.y) * cl.y
                                 + sigf(accFR[mt][a+1] + pf.y) * cr.y;
                        float hx = sigf(accO[mt][a]   + po.x) * tanha(cx);
                        float hy = sigf(accO[mt][a+1] + po.y) * tanha(cy);

                        int gg = sg[m];
                        *(float2*)&g_c[gg * 128 + c0] = make_float2(cx, cy);
                        *(float2*)&g_h[gg * 128 + c0] = make_float2(hx, hy);
                        if (l == 10)
                            *(float2*)&out[(gg >> 10) * 128 + c0] = make_float2(hx, hy);
                    }
            }
        }
    }
}

// ---------------------------------------------------------------------------
extern "C" void kernel_launch(void* const* d_in, const int* in_sizes, int n_in,
                              void* d_out, int out_size)
{
    const void* feats  = d_in[0];
    const float* emb   = (const float*)d_in[4];
    const float* sortt = (const float*)d_in[5];
    const float* pe    = (const float*)d_in[6];
    const float* Wiou  = (const float*)d_in[7];
    const float* Uiou  = (const float*)d_in[8];
    const float* biou  = (const float*)d_in[9];
    const float* Wf    = (const float*)d_in[10];
    const float* Uf    = (const float*)d_in[11];
    const float* bf    = (const float*)d_in[12];
    float* out = (float*)d_out;

    cudaFuncSetAttribute(k2_tree, cudaFuncAttributeMaxDynamicSharedMemorySize, SMEMSZ);

    kd_detect<<<1, 32>>>((const int*)feats);
    k0_tables<<<761, 512>>>(emb, sortt, pe, Wiou, Wf, biou, bf);
    k0b_pack<<<256, 256>>>(Uiou, Uf);
    k1_leaves<<<16384, 256>>>(feats);

    // All internal levels in one persistent launch: block = tree.
    k2_tree<<<NTREES, 256, SMEMSZ>>>(feats, out);
}

// round 10
// speedup vs baseline: 3.7813x; 1.3153x over previous
#include <cuda_runtime.h>
#include <cuda_fp16.h>
#include <cstdint>

#define NTREES 256
#define NPT    1024
#define NN     (NTREES * NPT)          // 262144 nodes
#define VOCAB  5000
#define SORTV  64
#define NPOS   1024
#define TCOLS  512                     // 384 iou cols + 128 f cols
#define BM     64
#define PAD2   68                      // padded row stride in uint32 (half2) words

// smem: sHL[64*68], sHR[64*68] packed half2 words
#define SMEMSZ  (2 * 64 * PAD2 * 4)    // 34816 bytes

// Device-global scratch (allocation-free per harness rules)
__device__ unsigned g_hH[NN * 64];     // h in fp16 pairs: 64 half2 words/node (64 MB)
__device__ float    g_c[NN * 128];     // c in fp32 (128 MB)
__device__ float    g_Ttok[VOCAB * TCOLS];
__device__ float    g_Tsort[SORTV * TCOLS];
__device__ float    g_Tpos[NPOS * TCOLS];
__device__ unsigned g_Upk[64 * 8 * 64];   // fp16 B frags: [nf(64)][ks16(8)][64 words]
__device__ int      g_is64;

__device__ __forceinline__ float tanha(float x) {
    float r;
    asm("tanh.approx.f32 %0, %1;" : "=f"(r) : "f"(x));
    return r;
}
__device__ __forceinline__ float sigf(float x) {
    return fmaf(0.5f, tanha(0.5f * x), 0.5f);
}
__device__ __forceinline__ unsigned packh2(float a, float b) {
    __half2 h = __floats2half2_rn(a, b);
    return *(unsigned*)&h;
}
__device__ __forceinline__ unsigned addh2(unsigned a, unsigned b) {
    __half2 r = __hadd2(*(__half2*)&a, *(__half2*)&b);
    return *(unsigned*)&r;
}

#define MMA16(ACC, A0, A1, A2, A3, B)                                          \
    asm volatile(                                                              \
        "mma.sync.aligned.m16n8k16.row.col.f32.f16.f16.f32 "                   \
        "{%0,%1,%2,%3}, {%4,%5,%6,%7}, {%8,%9}, {%0,%1,%2,%3};\n"              \
        : "+f"(ACC[0]), "+f"(ACC[1]), "+f"(ACC[2]), "+f"(ACC[3])               \
        : "r"(A0), "r"(A1), "r"(A2), "r"(A3), "r"(B.x), "r"(B.y))

// Feature fetch for int32 or int64 feature buffers.
__device__ __forceinline__ int3 getfeat(const void* f, int g)
{
    if (g_is64) {
        const long long* p = (const long long*)f;
        return make_int3((int)p[3 * g], (int)p[3 * g + 1], (int)p[3 * g + 2]);
    }
    const int* p = (const int*)f;
    return make_int3(p[3 * g], p[3 * g + 1], p[3 * g + 2]);
}

// ---------------------------------------------------------------------------
// Dtype detection: one warp ballots 32 odd 32-bit words.
// ---------------------------------------------------------------------------
__global__ void kd_detect(const int* f)
{
    unsigned any = __ballot_sync(0xffffffffu, f[threadIdx.x * 2 + 1] != 0);
    if (threadIdx.x == 0) g_is64 = (any == 0u) ? 1 : 0;
}

// ---------------------------------------------------------------------------
// K0: projection tables (embedding @ W factored through the three tables).
// ---------------------------------------------------------------------------
__global__ void k0_tables(const float* __restrict__ emb,
                          const float* __restrict__ sortt,
                          const float* __restrict__ pe,
                          const float* __restrict__ Wiou,
                          const float* __restrict__ Wf,
                          const float* __restrict__ biou,
                          const float* __restrict__ bf)
{
    __shared__ float se[8][64];
    int b = blockIdx.x;
    int j = threadIdx.x;

    const float* src; int wbase; float* dst; bool addb;
    if (b < 625)      { int r0 = b * 8;         src = emb   + r0 * 64; wbase = 0;   dst = g_Ttok  + r0 * TCOLS; addb = false; }
    else if (b < 633) { int r0 = (b - 625) * 8; src = sortt + r0 * 64; wbase = 64;  dst = g_Tsort + r0 * TCOLS; addb = false; }
    else              { int r0 = (b - 633) * 8; src = pe    + r0 * 64; wbase = 128; dst = g_Tpos  + r0 * TCOLS; addb = true;  }

    se[j >> 6][j & 63] = src[j];
    __syncthreads();

    float acc[8];
#pragma unroll
    for (int r = 0; r < 8; r++) acc[r] = 0.0f;

    float bias = 0.0f;
    if (j < 384) {
#pragma unroll 8
        for (int k = 0; k < 64; k++) {
            float w = Wiou[(wbase + k) * 384 + j];
#pragma unroll
            for (int r = 0; r < 8; r++) acc[r] += se[r][k] * w;
        }
        if (addb) bias = biou[j];
    } else {
        int jj = j - 384;
#pragma unroll 8
        for (int k = 0; k < 64; k++) {
            float w = Wf[(wbase + k) * 128 + jj];
#pragma unroll
            for (int r = 0; r < 8; r++) acc[r] += se[r][k] * w;
        }
        if (addb) bias = bf[jj];
    }
#pragma unroll
    for (int r = 0; r < 8; r++) dst[r * TCOLS + j] = acc[r] + bias;
}

// ---------------------------------------------------------------------------
// K0b: pack U = [U_iou | U_f] into m16n8k16 fp16 B-fragment order.
// Fragment (nf, ks16), word w: lane=w>>1, sel=w&1; halves at
//   k = ks16*16 + 2*(lane&3) + 8*sel + {0,1}, col = nf*8 + (lane>>2).
// ---------------------------------------------------------------------------
__global__ void k0b_pack(const float* __restrict__ Uiou, const float* __restrict__ Uf)
{
    int idx = blockIdx.x * 256 + threadIdx.x;   // 0..32767
    int f = idx >> 6, w = idx & 63;
    int nf = f >> 3, ks16 = f & 7;
    int lane = w >> 1, sel = w & 1;
    int kb = ks16 * 16 + 2 * (lane & 3) + 8 * sel;
    int c = lane >> 2;
    float lo, hi;
    if (nf < 48) {
        lo = Uiou[kb * 384 + nf * 8 + c];
        hi = Uiou[(kb + 1) * 384 + nf * 8 + c];
    } else {
        lo = Uf[kb * 128 + (nf - 48) * 8 + c];
        hi = Uf[(kb + 1) * 128 + (nf - 48) * 8 + c];
    }
    g_Upk[idx] = packh2(lo, hi);
}

// ---------------------------------------------------------------------------
// K1: leaves, float4-vectorized. 256 threads = 8 leaves x 32 cols4.
// h written as fp16 pairs, c as fp32.
// ---------------------------------------------------------------------------
__global__ void k1_leaves(const void* __restrict__ feats)
{
    int tid = threadIdx.x;
    int q   = tid & 31;
    int L   = blockIdx.x * 8 + (tid >> 5);
    int t   = L >> 9;
    int i   = 512 + (L & 511);
    int g   = t * NPT + i;

    int3 ft = getfeat(feats, g);

    const float* Pt = g_Ttok  + ft.x * TCOLS + q * 4;
    const float* Ps = g_Tsort + ft.y * TCOLS + q * 4;
    const float* Pp = g_Tpos  + ft.z * TCOLS + q * 4;

    float4 a, b, d, pi, po, pu;
    a = *(const float4*)Pt;        b = *(const float4*)Ps;        d = *(const float4*)Pp;
    pi = make_float4(a.x+b.x+d.x, a.y+b.y+d.y, a.z+b.z+d.z, a.w+b.w+d.w);
    a = *(const float4*)(Pt+128);  b = *(const float4*)(Ps+128);  d = *(const float4*)(Pp+128);
    po = make_float4(a.x+b.x+d.x, a.y+b.y+d.y, a.z+b.z+d.z, a.w+b.w+d.w);
    a = *(const float4*)(Pt+256);  b = *(const float4*)(Ps+256);  d = *(const float4*)(Pp+256);
    pu = make_float4(a.x+b.x+d.x, a.y+b.y+d.y, a.z+b.z+d.z, a.w+b.w+d.w);

    float4 cv = make_float4(sigf(pi.x) * tanha(pu.x), sigf(pi.y) * tanha(pu.y),
                            sigf(pi.z) * tanha(pu.z), sigf(pi.w) * tanha(pu.w));
    float4 hv = make_float4(sigf(po.x) * tanha(cv.x), sigf(po.y) * tanha(cv.y),
                            sigf(po.z) * tanha(cv.z), sigf(po.w) * tanha(cv.w));
    *(float4*)&g_c[g * 128 + q * 4] = cv;
    uint2 hw = make_uint2(packh2(hv.x, hv.y), packh2(hv.z, hv.w));
    *(uint2*)&g_hH[g * 64 + q * 2] = hw;
}

// ---------------------------------------------------------------------------
// K2: persistent per-tree kernel, fp16 m16n8k16 MMA. Block = one tree;
// levels 1..10 bottom-up, <=64-node chunks. One cg per pass, 4 m-tiles
// share each B fragment load; hs formed via HADD2 from hl+hr.
// ---------------------------------------------------------------------------
__global__ __launch_bounds__(256, 2) void k2_tree(
    const void* __restrict__ feats,
    float* __restrict__ out)
{
    extern __shared__ unsigned smu[];
    unsigned* sHL = smu;
    unsigned* sHR = smu + 64 * PAD2;

    __shared__ int sg[BM], sgl[BM], sgr[BM], stok[BM], ssrt[BM], spos[BM];

    int tid  = threadIdx.x;
    int lane = tid & 31;
    int w    = tid >> 5;
    int g4   = lane >> 2, tg = lane & 3;
    int tb   = blockIdx.x * NPT;       // tree base node

    for (int l = 1; l <= 10; l++) {
        int cnt = (l == 1) ? 1 : (1 << (10 - l));
        int beg = (l == 1) ? 511 : cnt - 1;

        for (int ch = 0; ch < cnt; ch += BM) {
            int n = cnt - ch; if (n > BM) n = BM;   // valid rows this chunk

            __syncthreads();   // protect smem/index arrays from prior chunk readers
            if (tid < BM) {
                int m = (tid < n) ? tid : 0;        // clamp padding rows
                int i = beg + ch + m;
                int g = tb + i;
                sg[tid]  = g;
                sgl[tid] = tb + 2 * i + 1;
                int rr2 = 2 * i + 2;
                sgr[tid] = (rr2 < NPT) ? tb + rr2 : -1;   // node 511: single child
                int3 ft = getfeat(feats, g);
                stok[tid] = ft.x;
                ssrt[tid] = ft.y;
                spos[tid] = ft.z;
            }
            __syncthreads();

            // Stage child h tiles (fp16 pair words; no conversion needed)
#pragma unroll
            for (int r4 = 0; r4 < 4; r4++) {
                int idx = tid + r4 * 256;      // 0..1023 = m*16 + q
                int m = idx >> 4, q = idx & 15;
                uint4 hl = *(const uint4*)&g_hH[sgl[m] * 64 + q * 4];
                uint4 hr = make_uint4(0u, 0u, 0u, 0u);
                int gr = sgr[m];
                if (gr >= 0) hr = *(const uint4*)&g_hH[gr * 64 + q * 4];
                *(uint4*)&sHL[m * PAD2 + q * 4] = hl;
                *(uint4*)&sHR[m * PAD2 + q * 4] = hr;
            }
            __syncthreads();

            // Two col-groups per warp; 4 m-tiles (64 rows) share each B load.
#pragma unroll 1
            for (int cgi = 0; cgi < 2; cgi++) {
                int cg = w + 8 * cgi;          // 0..15

                float accI[4][4], accO[4][4], accU[4][4], accFL[4][4], accFR[4][4];
#pragma unroll
                for (int mt = 0; mt < 4; mt++)
#pragma unroll
                    for (int e = 0; e < 4; e++) {
                        accI[mt][e] = accO[mt][e] = accU[mt][e] = 0.0f;
                        accFL[mt][e] = accFR[mt][e] = 0.0f;
                    }

#pragma unroll 1
                for (int ks = 0; ks < 8; ks++) {
                    uint2 bi = *(const uint2*)&g_Upk[((cg     ) * 8 + ks) * 64 + 2 * lane];
                    uint2 bo = *(const uint2*)&g_Upk[((16 + cg) * 8 + ks) * 64 + 2 * lane];
                    uint2 bu = *(const uint2*)&g_Upk[((32 + cg) * 8 + ks) * 64 + 2 * lane];
                    uint2 bf = *(const uint2*)&g_Upk[((48 + cg) * 8 + ks) * 64 + 2 * lane];
#pragma unroll
                    for (int mt = 0; mt < 4; mt++) {
                        if (mt * 16 < n) {
                            int rowoff = (mt * 16 + g4) * PAD2 + 8 * ks + tg;
                            unsigned l0 = sHL[rowoff],     l1 = sHL[rowoff + 8 * PAD2];
                            unsigned l2 = sHL[rowoff + 4], l3 = sHL[rowoff + 8 * PAD2 + 4];
                            unsigned r0 = sHR[rowoff],     r1 = sHR[rowoff + 8 * PAD2];
                            unsigned r2 = sHR[rowoff + 4], r3 = sHR[rowoff + 8 * PAD2 + 4];
                            unsigned s0 = addh2(l0, r0),   s1 = addh2(l1, r1);
                            unsigned s2 = addh2(l2, r2),   s3 = addh2(l3, r3);
                            MMA16(accI[mt], s0, s1, s2, s3, bi);
                            MMA16(accO[mt], s0, s1, s2, s3, bo);
                            MMA16(accU[mt], s0, s1, s2, s3, bu);
                            MMA16(accFL[mt], l0, l1, l2, l3, bf);
                            MMA16(accFR[mt], r0, r1, r2, r3, bf);
                        }
                    }
                }

                // Register epilogue: rows m = mt*16 + rr*8 + g4, cols c0, c0+1.
                int c0 = cg * 8 + 2 * tg;
#pragma unroll
                for (int mt = 0; mt < 4; mt++)
#pragma unroll
                    for (int rr = 0; rr < 2; rr++) {
                        int m = mt * 16 + rr * 8 + g4;
                        if (m >= n) continue;
                        int a = rr * 2;
                        const float* Tt = g_Ttok  + stok[m] * TCOLS + c0;
                        const float* Ts = g_Tsort + ssrt[m] * TCOLS + c0;
                        const float* Tp = g_Tpos  + spos[m] * TCOLS + c0;

                        float2 t0, t1, t2;
                        t0 = *(const float2*)Tt;        t1 = *(const float2*)Ts;        t2 = *(const float2*)Tp;
                        float2 pi = make_float2(t0.x + t1.x + t2.x, t0.y + t1.y + t2.y);
                        t0 = *(const float2*)(Tt+128);  t1 = *(const float2*)(Ts+128);  t2 = *(const float2*)(Tp+128);
                        float2 po = make_float2(t0.x + t1.x + t2.x, t0.y + t1.y + t2.y);
                        t0 = *(const float2*)(Tt+256);  t1 = *(const float2*)(Ts+256);  t2 = *(const float2*)(Tp+256);
                        float2 pu = make_float2(t0.x + t1.x + t2.x, t0.y + t1.y + t2.y);
                        t0 = *(const float2*)(Tt+384);  t1 = *(const float2*)(Ts+384);  t2 = *(const float2*)(Tp+384);
                        float2 pf = make_float2(t0.x + t1.x + t2.x, t0.y + t1.y + t2.y);

                        float2 cl = *(const float2*)&g_c[sgl[m] * 128 + c0];
                        float2 cr = make_float2(0.f, 0.f);
                        int gr = sgr[m];
                        if (gr >= 0) cr = *(const float2*)&g_c[gr * 128 + c0];

                        float cx = sigf(accI[mt][a]   + pi.x) * tanha(accU[mt][a]   + pu.x)
                                 + sigf(accFL[mt][a]  + pf.x) * cl.x
                                 + sigf(accFR[mt][a]  + pf.x) * cr.x;
                        float cy = sigf(accI[mt][a+1] + pi.y) * tanha(accU[mt][a+1] + pu.y)
                                 + sigf(accFL[mt][a+1] + pf.y) * cl.y
                                 + sigf(accFR[mt][a+1] + pf.y) * cr.y;
                        float hx = sigf(accO[mt][a]   + po.x) * tanha(cx);
                        float hy = sigf(accO[mt][a+1] + po.y) * tanha(cy);

                        int gg = sg[m];
                        *(float2*)&g_c[gg * 128 + c0] = make_float2(cx, cy);
                        g_hH[gg * 64 + (c0 >> 1)] = packh2(hx, hy);
                        if (l == 10)
                            *(float2*)&out[(gg >> 10) * 128 + c0] = make_float2(hx, hy);
                    }
            }
        }
    }
}

// ---------------------------------------------------------------------------
extern "C" void kernel_launch(void* const* d_in, const int* in_sizes, int n_in,
                              void* d_out, int out_size)
{
    const void* feats  = d_in[0];
    const float* emb   = (const float*)d_in[4];
    const float* sortt = (const float*)d_in[5];
    const float* pe    = (const float*)d_in[6];
    const float* Wiou  = (const float*)d_in[7];
    const float* Uiou  = (const float*)d_in[8];
    const float* biou  = (const float*)d_in[9];
    const float* Wf    = (const float*)d_in[10];
    const float* Uf    = (const float*)d_in[11];
    const float* bf    = (const float*)d_in[12];
    float* out = (float*)d_out;

    cudaFuncSetAttribute(k2_tree, cudaFuncAttributeMaxDynamicSharedMemorySize, SMEMSZ);

    kd_detect<<<1, 32>>>((const int*)feats);
    k0_tables<<<761, 512>>>(emb, sortt, pe, Wiou, Wf, biou, bf);
    k0b_pack<<<128, 256>>>(Uiou, Uf);
    k1_leaves<<<16384, 256>>>(feats);

    // All internal levels in one persistent launch: block = tree.
    k2_tree<<<NTREES, 256, SMEMSZ>>>(feats, out);
}

// round 11
// speedup vs baseline: 4.0281x; 1.0652x over previous
#include <cuda_runtime.h>
#include <cuda_fp16.h>
#include <cstdint>

#define NTREES 256
#define NPT    1024
#define NN     (NTREES * NPT)          // 262144 nodes
#define VOCAB  5000
#define SORTV  64
#define NPOS   1024
#define TCOLS  512                     // 384 iou cols + 128 f cols
#define BM     64
#define PAD2   68                      // padded row stride in uint32 (half2) words

// smem: sHL[64*68], sHR[64*68] packed half2 words
#define SMEMSZ  (2 * 64 * PAD2 * 4)    // 34816 bytes

// Device-global scratch (allocation-free per harness rules)
__device__ unsigned g_hH[NN * 64];     // h in fp16 pairs (64 MB)
__device__ float    g_c[NN * 128];     // c in fp32 (128 MB)
__device__ __half   g_Ttok[VOCAB * TCOLS];   // fp16 tables (6.5 MB total)
__device__ __half   g_Tsort[SORTV * TCOLS];
__device__ __half   g_Tpos[NPOS * TCOLS];
__device__ unsigned g_Upk[64 * 8 * 64];   // fp16 B frags: [nf(64)][ks16(8)][64 words]
__device__ int      g_is64;

__device__ __forceinline__ float tanha(float x) {
    float r;
    asm("tanh.approx.f32 %0, %1;" : "=f"(r) : "f"(x));
    return r;
}
__device__ __forceinline__ float sigf(float x) {
    return fmaf(0.5f, tanha(0.5f * x), 0.5f);
}
__device__ __forceinline__ unsigned packh2(float a, float b) {
    __half2 h = __floats2half2_rn(a, b);
    return *(unsigned*)&h;
}
__device__ __forceinline__ unsigned addh2(unsigned a, unsigned b) {
    __half2 r = __hadd2(*(__half2*)&a, *(__half2*)&b);
    return *(unsigned*)&r;
}
// sum of three fp16 table entries (2 cols) -> float2
__device__ __forceinline__ float2 tbl3v2(const __half* t, const __half* s, const __half* p) {
    float2 a = __half22float2(*(const __half2*)t);
    float2 b = __half22float2(*(const __half2*)s);
    float2 c = __half22float2(*(const __half2*)p);
    return make_float2(a.x + b.x + c.x, a.y + b.y + c.y);
}
// sum of three fp16 table entries (4 cols) -> float4
__device__ __forceinline__ float4 tbl3v4(const __half* t, const __half* s, const __half* p) {
    uint2 wa = *(const uint2*)t, wb = *(const uint2*)s, wc = *(const uint2*)p;
    float2 a0 = __half22float2(*(__half2*)&wa.x), a1 = __half22float2(*(__half2*)&wa.y);
    float2 b0 = __half22float2(*(__half2*)&wb.x), b1 = __half22float2(*(__half2*)&wb.y);
    float2 c0 = __half22float2(*(__half2*)&wc.x), c1 = __half22float2(*(__half2*)&wc.y);
    return make_float4(a0.x + b0.x + c0.x, a0.y + b0.y + c0.y,
                       a1.x + b1.x + c1.x, a1.y + b1.y + c1.y);
}

#define MMA16(ACC, A0, A1, A2, A3, B)                                          \
    asm volatile(                                                              \
        "mma.sync.aligned.m16n8k16.row.col.f32.f16.f16.f32 "                   \
        "{%0,%1,%2,%3}, {%4,%5,%6,%7}, {%8,%9}, {%0,%1,%2,%3};\n"              \
        : "+f"(ACC[0]), "+f"(ACC[1]), "+f"(ACC[2]), "+f"(ACC[3])               \
        : "r"(A0), "r"(A1), "r"(A2), "r"(A3), "r"(B.x), "r"(B.y))

// Feature fetch for int32 or int64 feature buffers.
__device__ __forceinline__ int3 getfeat(const void* f, int g)
{
    if (g_is64) {
        const long long* p = (const long long*)f;
        return make_int3((int)p[3 * g], (int)p[3 * g + 1], (int)p[3 * g + 2]);
    }
    const int* p = (const int*)f;
    return make_int3(p[3 * g], p[3 * g + 1], p[3 * g + 2]);
}

// ---------------------------------------------------------------------------
// Dtype detection: one warp ballots 32 odd 32-bit words.
// ---------------------------------------------------------------------------
__global__ void kd_detect(const int* f)
{
    unsigned any = __ballot_sync(0xffffffffu, f[threadIdx.x * 2 + 1] != 0);
    if (threadIdx.x == 0) g_is64 = (any == 0u) ? 1 : 0;
}

// ---------------------------------------------------------------------------
// K0: projection tables (embedding @ W factored through the three tables),
// written in fp16.
// ---------------------------------------------------------------------------
__global__ void k0_tables(const float* __restrict__ emb,
                          const float* __restrict__ sortt,
                          const float* __restrict__ pe,
                          const float* __restrict__ Wiou,
                          const float* __restrict__ Wf,
                          const float* __restrict__ biou,
                          const float* __restrict__ bf)
{
    __shared__ float se[8][64];
    int b = blockIdx.x;
    int j = threadIdx.x;

    const float* src; int wbase; __half* dst; bool addb;
    if (b < 625)      { int r0 = b * 8;         src = emb   + r0 * 64; wbase = 0;   dst = g_Ttok  + r0 * TCOLS; addb = false; }
    else if (b < 633) { int r0 = (b - 625) * 8; src = sortt + r0 * 64; wbase = 64;  dst = g_Tsort + r0 * TCOLS; addb = false; }
    else              { int r0 = (b - 633) * 8; src = pe    + r0 * 64; wbase = 128; dst = g_Tpos  + r0 * TCOLS; addb = true;  }

    se[j >> 6][j & 63] = src[j];
    __syncthreads();

    float acc[8];
#pragma unroll
    for (int r = 0; r < 8; r++) acc[r] = 0.0f;

    float bias = 0.0f;
    if (j < 384) {
#pragma unroll 8
        for (int k = 0; k < 64; k++) {
            float w = Wiou[(wbase + k) * 384 + j];
#pragma unroll
            for (int r = 0; r < 8; r++) acc[r] += se[r][k] * w;
        }
        if (addb) bias = biou[j];
    } else {
        int jj = j - 384;
#pragma unroll 8
        for (int k = 0; k < 64; k++) {
            float w = Wf[(wbase + k) * 128 + jj];
#pragma unroll
            for (int r = 0; r < 8; r++) acc[r] += se[r][k] * w;
        }
        if (addb) bias = bf[jj];
    }
#pragma unroll
    for (int r = 0; r < 8; r++) dst[r * TCOLS + j] = __float2half(acc[r] + bias);
}

// ---------------------------------------------------------------------------
// K0b: pack U = [U_iou | U_f] into m16n8k16 fp16 B-fragment order.
// ---------------------------------------------------------------------------
__global__ void k0b_pack(const float* __restrict__ Uiou, const float* __restrict__ Uf)
{
    int idx = blockIdx.x * 256 + threadIdx.x;   // 0..32767
    int f = idx >> 6, w = idx & 63;
    int nf = f >> 3, ks16 = f & 7;
    int lane = w >> 1, sel = w & 1;
    int kb = ks16 * 16 + 2 * (lane & 3) + 8 * sel;
    int c = lane >> 2;
    float lo, hi;
    if (nf < 48) {
        lo = Uiou[kb * 384 + nf * 8 + c];
        hi = Uiou[(kb + 1) * 384 + nf * 8 + c];
    } else {
        lo = Uf[kb * 128 + (nf - 48) * 8 + c];
        hi = Uf[(kb + 1) * 128 + (nf - 48) * 8 + c];
    }
    g_Upk[idx] = packh2(lo, hi);
}

// ---------------------------------------------------------------------------
// K1: leaves. 256 threads = 8 leaves x 32 cols4. fp16 table reads,
// h written as fp16 pairs, c as fp32.
// ---------------------------------------------------------------------------
__global__ void k1_leaves(const void* __restrict__ feats)
{
    int tid = threadIdx.x;
    int q   = tid & 31;
    int L   = blockIdx.x * 8 + (tid >> 5);
    int t   = L >> 9;
    int i   = 512 + (L & 511);
    int g   = t * NPT + i;

    int3 ft = getfeat(feats, g);

    const __half* Pt = g_Ttok  + ft.x * TCOLS + q * 4;
    const __half* Ps = g_Tsort + ft.y * TCOLS + q * 4;
    const __half* Pp = g_Tpos  + ft.z * TCOLS + q * 4;

    float4 pi = tbl3v4(Pt,       Ps,       Pp);
    float4 po = tbl3v4(Pt + 128, Ps + 128, Pp + 128);
    float4 pu = tbl3v4(Pt + 256, Ps + 256, Pp + 256);

    float4 cv = make_float4(sigf(pi.x) * tanha(pu.x), sigf(pi.y) * tanha(pu.y),
                            sigf(pi.z) * tanha(pu.z), sigf(pi.w) * tanha(pu.w));
    float4 hv = make_float4(sigf(po.x) * tanha(cv.x), sigf(po.y) * tanha(cv.y),
                            sigf(po.z) * tanha(cv.z), sigf(po.w) * tanha(cv.w));
    *(float4*)&g_c[g * 128 + q * 4] = cv;
    uint2 hw = make_uint2(packh2(hv.x, hv.y), packh2(hv.z, hv.w));
    *(uint2*)&g_hH[g * 64 + q * 2] = hw;
}

// B fragment load helper
#define LDB(NF, KS, V) \
    V = *(const uint2*)&g_Upk[(((NF)) * 8 + (KS)) * 64 + 2 * lane]

// ---------------------------------------------------------------------------
// K2: persistent per-tree kernel, fp16 m16n8k16 MMA with register-pipelined
// B fragments (cyclic double-buffer live across chunks — frags identical
// every chunk, so each chunk's first iteration was prefetched by the
// previous chunk's last).
// ---------------------------------------------------------------------------
__global__ __launch_bounds__(256, 2) void k2_tree(
    const void* __restrict__ feats,
    float* __restrict__ out)
{
    extern __shared__ unsigned smu[];
    unsigned* sHL = smu;
    unsigned* sHR = smu + 64 * PAD2;

    __shared__ int sg[BM], sgl[BM], sgr[BM], stok[BM], ssrt[BM], spos[BM];

    int tid  = threadIdx.x;
    int lane = tid & 31;
    int w    = tid >> 5;
    int g4   = lane >> 2, tg = lane & 3;
    int tb   = blockIdx.x * NPT;       // tree base node

    // Prime the B pipeline (cgi=0, ks=0 position)
    uint2 Bi, Bo, Bu, Bf;
    LDB(w,      0, Bi);
    LDB(16 + w, 0, Bo);
    LDB(32 + w, 0, Bu);
    LDB(48 + w, 0, Bf);

    for (int l = 1; l <= 10; l++) {
        int cnt = (l == 1) ? 1 : (1 << (10 - l));
        int beg = (l == 1) ? 511 : cnt - 1;

        for (int ch = 0; ch < cnt; ch += BM) {
            int n = cnt - ch; if (n > BM) n = BM;   // valid rows this chunk

            __syncthreads();   // protect smem/index arrays from prior chunk readers
            if (tid < BM) {
                int m = (tid < n) ? tid : 0;        // clamp padding rows
                int i = beg + ch + m;
                int g = tb + i;
                sg[tid]  = g;
                sgl[tid] = tb + 2 * i + 1;
                int rr2 = 2 * i + 2;
                sgr[tid] = (rr2 < NPT) ? tb + rr2 : -1;   // node 511: single child
                int3 ft = getfeat(feats, g);
                stok[tid] = ft.x;
                ssrt[tid] = ft.y;
                spos[tid] = ft.z;
            }
            __syncthreads();

            // Stage child h tiles (fp16 pair words)
#pragma unroll
            for (int r4 = 0; r4 < 4; r4++) {
                int idx = tid + r4 * 256;      // 0..1023 = m*16 + q
                int m = idx >> 4, q = idx & 15;
                uint4 hl = *(const uint4*)&g_hH[sgl[m] * 64 + q * 4];
                uint4 hr = make_uint4(0u, 0u, 0u, 0u);
                int gr = sgr[m];
                if (gr >= 0) hr = *(const uint4*)&g_hH[gr * 64 + q * 4];
                *(uint4*)&sHL[m * PAD2 + q * 4] = hl;
                *(uint4*)&sHR[m * PAD2 + q * 4] = hr;
            }
            __syncthreads();

            // Two col-groups per warp; 4 m-tiles share each B fragment.
#pragma unroll 1
            for (int cgi = 0; cgi < 2; cgi++) {
                int cg = w + 8 * cgi;          // 0..15

                float accI[4][4], accO[4][4], accU[4][4], accFL[4][4], accFR[4][4];
#pragma unroll
                for (int mt = 0; mt < 4; mt++)
#pragma unroll
                    for (int e = 0; e < 4; e++) {
                        accI[mt][e] = accO[mt][e] = accU[mt][e] = 0.0f;
                        accFL[mt][e] = accFR[mt][e] = 0.0f;
                    }

#pragma unroll 1
                for (int ks = 0; ks < 8; ks++) {
                    // prefetch next position (cyclic over 16: wraps to next
                    // chunk's first iteration — identical fragments)
                    int np = (cgi * 8 + ks + 1) & 15;
                    int ncg = w + 8 * (np >> 3), nks = np & 7;
                    uint2 Ni, No, Nu, Nf;
                    LDB(ncg,      nks, Ni);
                    LDB(16 + ncg, nks, No);
                    LDB(32 + ncg, nks, Nu);
                    LDB(48 + ncg, nks, Nf);

#pragma unroll
                    for (int mt = 0; mt < 4; mt++) {
                        if (mt * 16 < n) {
                            int rowoff = (mt * 16 + g4) * PAD2 + 8 * ks + tg;
                            unsigned l0 = sHL[rowoff],     l1 = sHL[rowoff + 8 * PAD2];
                            unsigned l2 = sHL[rowoff + 4], l3 = sHL[rowoff + 8 * PAD2 + 4];
                            unsigned r0 = sHR[rowoff],     r1 = sHR[rowoff + 8 * PAD2];
                            unsigned r2 = sHR[rowoff + 4], r3 = sHR[rowoff + 8 * PAD2 + 4];
                            unsigned s0 = addh2(l0, r0),   s1 = addh2(l1, r1);
                            unsigned s2 = addh2(l2, r2),   s3 = addh2(l3, r3);
                            MMA16(accI[mt], s0, s1, s2, s3, Bi);
                            MMA16(accO[mt], s0, s1, s2, s3, Bo);
                            MMA16(accU[mt], s0, s1, s2, s3, Bu);
                            MMA16(accFL[mt], l0, l1, l2, l3, Bf);
                            MMA16(accFR[mt], r0, r1, r2, r3, Bf);
                        }
                    }
                    Bi = Ni; Bo = No; Bu = Nu; Bf = Nf;
                }

                // Register epilogue: rows m = mt*16 + rr*8 + g4, cols c0, c0+1.
                int c0 = cg * 8 + 2 * tg;
#pragma unroll
                for (int mt = 0; mt < 4; mt++)
#pragma unroll
                    for (int rr = 0; rr < 2; rr++) {
                        int m = mt * 16 + rr * 8 + g4;
                        if (m >= n) continue;
                        int a = rr * 2;
                        const __half* Tt = g_Ttok  + stok[m] * TCOLS + c0;
                        const __half* Ts = g_Tsort + ssrt[m] * TCOLS + c0;
                        const __half* Tp = g_Tpos  + spos[m] * TCOLS + c0;

                        float2 pi = tbl3v2(Tt,       Ts,       Tp);
                        float2 po = tbl3v2(Tt + 128, Ts + 128, Tp + 128);
                        float2 pu = tbl3v2(Tt + 256, Ts + 256, Tp + 256);
                        float2 pf = tbl3v2(Tt + 384, Ts + 384, Tp + 384);

                        float2 cl = *(const float2*)&g_c[sgl[m] * 128 + c0];
                        float2 cr = make_float2(0.f, 0.f);
                        int gr = sgr[m];
                        if (gr >= 0) cr = *(const float2*)&g_c[gr * 128 + c0];

                        float cx = sigf(accI[mt][a]   + pi.x) * tanha(accU[mt][a]   + pu.x)
                                 + sigf(accFL[mt][a]  + pf.x) * cl.x
                                 + sigf(accFR[mt][a]  + pf.x) * cr.x;
                        float cy = sigf(accI[mt][a+1] + pi.y) * tanha(accU[mt][a+1] + pu.y)
                                 + sigf(accFL[mt][a+1] + pf.y) * cl.y
                                 + sigf(accFR[mt][a+1] + pf.y) * cr.y;
                        float hx = sigf(accO[mt][a]   + po.x) * tanha(cx);
                        float hy = sigf(accO[mt][a+1] + po.y) * tanha(cy);

                        int gg = sg[m];
                        *(float2*)&g_c[gg * 128 + c0] = make_float2(cx, cy);
                        g_hH[gg * 64 + (c0 >> 1)] = packh2(hx, hy);
                        if (l == 10)
                            *(float2*)&out[(gg >> 10) * 128 + c0] = make_float2(hx, hy);
                    }
            }
        }
    }
}

// ---------------------------------------------------------------------------
extern "C" void kernel_launch(void* const* d_in, const int* in_sizes, int n_in,
                              void* d_out, int out_size)
{
    const void* feats  = d_in[0];
    const float* emb   = (const float*)d_in[4];
    const float* sortt = (const float*)d_in[5];
    const float* pe    = (const float*)d_in[6];
    const float* Wiou  = (const float*)d_in[7];
    const float* Uiou  = (const float*)d_in[8];
    const float* biou  = (const float*)d_in[9];
    const float* Wf    = (const float*)d_in[10];
    const float* Uf    = (const float*)d_in[11];
    const float* bf    = (const float*)d_in[12];
    float* out = (float*)d_out;

    cudaFuncSetAttribute(k2_tree, cudaFuncAttributeMaxDynamicSharedMemorySize, SMEMSZ);

    kd_detect<<<1, 32>>>((const int*)feats);
    k0_tables<<<761, 512>>>(emb, sortt, pe, Wiou, Wf, biou, bf);
    k0b_pack<<<128, 256>>>(Uiou, Uf);
    k1_leaves<<<16384, 256>>>(feats);

    // All internal levels in one persistent launch: block = tree.
    k2_tree<<<NTREES, 256, SMEMSZ>>>(feats, out);
}

// round 12
// speedup vs baseline: 4.1358x; 1.0268x over previous
#include <cuda_runtime.h>
#include <cuda_fp16.h>
#include <cstdint>

#define NTREES 256
#define NPT    1024
#define NN     (NTREES * NPT)          // 262144 nodes
#define VOCAB  5000
#define SORTV  64
#define NPOS   1024
#define TCOLS  512                     // 384 iou cols + 128 f cols
#define BM     64
#define PAD2   68                      // padded row stride in uint32 (half2) words

// smem: sHL[64*68], sHR[64*68] packed half2 words
#define SMEMSZ  (2 * 64 * PAD2 * 4)    // 34816 bytes

// Device-global scratch (allocation-free per harness rules)
__device__ unsigned g_hH[NN * 64];     // h in fp16 pairs (64 MB)
__device__ float    g_c[NN * 128];     // c in fp32 (128 MB)
__device__ __half   g_Ttok[VOCAB * TCOLS];   // fp16 tables (6.5 MB total)
__device__ __half   g_Tsort[SORTV * TCOLS];
__device__ __half   g_Tpos[NPOS * TCOLS];
__device__ unsigned g_Upk[64 * 8 * 64];   // fp16 B frags: [nf(64)][ks16(8)][64 words]
__device__ int      g_is64;

__device__ __forceinline__ float tanha(float x) {
    float r;
    asm("tanh.approx.f32 %0, %1;" : "=f"(r) : "f"(x));
    return r;
}
__device__ __forceinline__ float sigf(float x) {
    return fmaf(0.5f, tanha(0.5f * x), 0.5f);
}
__device__ __forceinline__ unsigned packh2(float a, float b) {
    __half2 h = __floats2half2_rn(a, b);
    return *(unsigned*)&h;
}
__device__ __forceinline__ unsigned addh2(unsigned a, unsigned b) {
    __half2 r = __hadd2(*(__half2*)&a, *(__half2*)&b);
    return *(unsigned*)&r;
}
__device__ __forceinline__ float2 tbl3v2(const __half* t, const __half* s, const __half* p) {
    float2 a = __half22float2(*(const __half2*)t);
    float2 b = __half22float2(*(const __half2*)s);
    float2 c = __half22float2(*(const __half2*)p);
    return make_float2(a.x + b.x + c.x, a.y + b.y + c.y);
}
__device__ __forceinline__ float4 tbl3v4(const __half* t, const __half* s, const __half* p) {
    uint2 wa = *(const uint2*)t, wb = *(const uint2*)s, wc = *(const uint2*)p;
    float2 a0 = __half22float2(*(__half2*)&wa.x), a1 = __half22float2(*(__half2*)&wa.y);
    float2 b0 = __half22float2(*(__half2*)&wb.x), b1 = __half22float2(*(__half2*)&wb.y);
    float2 c0 = __half22float2(*(__half2*)&wc.x), c1 = __half22float2(*(__half2*)&wc.y);
    return make_float4(a0.x + b0.x + c0.x, a0.y + b0.y + c0.y,
                       a1.x + b1.x + c1.x, a1.y + b1.y + c1.y);
}

#define MMA16(ACC, A0, A1, A2, A3, B)                                          \
    asm volatile(                                                              \
        "mma.sync.aligned.m16n8k16.row.col.f32.f16.f16.f32 "                   \
        "{%0,%1,%2,%3}, {%4,%5,%6,%7}, {%8,%9}, {%0,%1,%2,%3};\n"              \
        : "+f"(ACC[0]), "+f"(ACC[1]), "+f"(ACC[2]), "+f"(ACC[3])               \
        : "r"(A0), "r"(A1), "r"(A2), "r"(A3), "r"(B.x), "r"(B.y))

// ldmatrix x4: loads a0..a3 of one 16x16 f16 A tile (layout matches the
// previous 4x LDS.32 loads exactly).
__device__ __forceinline__ void ldsm4(unsigned& d0, unsigned& d1,
                                      unsigned& d2, unsigned& d3, uint32_t addr)
{
    asm volatile("ldmatrix.sync.aligned.m8n8.x4.shared.b16 {%0,%1,%2,%3}, [%4];"
                 : "=r"(d0), "=r"(d1), "=r"(d2), "=r"(d3) : "r"(addr));
}

__device__ __forceinline__ int3 getfeat(const void* f, int g)
{
    if (g_is64) {
        const long long* p = (const long long*)f;
        return make_int3((int)p[3 * g], (int)p[3 * g + 1], (int)p[3 * g + 2]);
    }
    const int* p = (const int*)f;
    return make_int3(p[3 * g], p[3 * g + 1], p[3 * g + 2]);
}

// ---------------------------------------------------------------------------
// K0a (fused): blocks 0..127 pack U fragments (256 thr); block 128 dtype
// detect. Independent of k0_tables.
// ---------------------------------------------------------------------------
__global__ void k0a_pack_detect(const float* __restrict__ Uiou,
                                const float* __restrict__ Uf,
                                const int* __restrict__ featsw)
{
    int b = blockIdx.x;
    int j = threadIdx.x;

    if (b == 128) {                    // dtype detect (one warp)
        if (j < 32) {
            unsigned any = __ballot_sync(0xffffffffu, featsw[j * 2 + 1] != 0);
            if (j == 0) g_is64 = (any == 0u) ? 1 : 0;
        }
        return;
    }

    int idx = b * 256 + j;             // 0..32767
    int f = idx >> 6, w = idx & 63;
    int nf = f >> 3, ks16 = f & 7;
    int lane = w >> 1, sel = w & 1;
    int kb = ks16 * 16 + 2 * (lane & 3) + 8 * sel;
    int c = lane >> 2;
    float lo, hi;
    if (nf < 48) {
        lo = Uiou[kb * 384 + nf * 8 + c];
        hi = Uiou[(kb + 1) * 384 + nf * 8 + c];
    } else {
        lo = Uf[kb * 128 + (nf - 48) * 8 + c];
        hi = Uf[(kb + 1) * 128 + (nf - 48) * 8 + c];
    }
    g_Upk[idx] = packh2(lo, hi);
}

// ---------------------------------------------------------------------------
// K0: projection tables in fp16 (unchanged).
// ---------------------------------------------------------------------------
__global__ void k0_tables(const float* __restrict__ emb,
                          const float* __restrict__ sortt,
                          const float* __restrict__ pe,
                          const float* __restrict__ Wiou,
                          const float* __restrict__ Wf,
                          const float* __restrict__ biou,
                          const float* __restrict__ bf)
{
    __shared__ float se[8][64];
    int b = blockIdx.x;
    int j = threadIdx.x;

    const float* src; int wbase; __half* dst; bool addb;
    if (b < 625)      { int r0 = b * 8;         src = emb   + r0 * 64; wbase = 0;   dst = g_Ttok  + r0 * TCOLS; addb = false; }
    else if (b < 633) { int r0 = (b - 625) * 8; src = sortt + r0 * 64; wbase = 64;  dst = g_Tsort + r0 * TCOLS; addb = false; }
    else              { int r0 = (b - 633) * 8; src = pe    + r0 * 64; wbase = 128; dst = g_Tpos  + r0 * TCOLS; addb = true;  }

    se[j >> 6][j & 63] = src[j];
    __syncthreads();

    float acc[8];
#pragma unroll
    for (int r = 0; r < 8; r++) acc[r] = 0.0f;

    float bias = 0.0f;
    if (j < 384) {
#pragma unroll 8
        for (int k = 0; k < 64; k++) {
            float w = Wiou[(wbase + k) * 384 + j];
#pragma unroll
            for (int r = 0; r < 8; r++) acc[r] += se[r][k] * w;
        }
        if (addb) bias = biou[j];
    } else {
        int jj = j - 384;
#pragma unroll 8
        for (int k = 0; k < 64; k++) {
            float w = Wf[(wbase + k) * 128 + jj];
#pragma unroll
            for (int r = 0; r < 8; r++) acc[r] += se[r][k] * w;
        }
        if (addb) bias = bf[jj];
    }
#pragma unroll
    for (int r = 0; r < 8; r++) dst[r * TCOLS + j] = __float2half(acc[r] + bias);
}

// ---------------------------------------------------------------------------
// K1: leaves (unchanged).
// ---------------------------------------------------------------------------
__global__ void k1_leaves(const void* __restrict__ feats)
{
    int tid = threadIdx.x;
    int q   = tid & 31;
    int L   = blockIdx.x * 8 + (tid >> 5);
    int t   = L >> 9;
    int i   = 512 + (L & 511);
    int g   = t * NPT + i;

    int3 ft = getfeat(feats, g);

    const __half* Pt = g_Ttok  + ft.x * TCOLS + q * 4;
    const __half* Ps = g_Tsort + ft.y * TCOLS + q * 4;
    const __half* Pp = g_Tpos  + ft.z * TCOLS + q * 4;

    float4 pi = tbl3v4(Pt,       Ps,       Pp);
    float4 po = tbl3v4(Pt + 128, Ps + 128, Pp + 128);
    float4 pu = tbl3v4(Pt + 256, Ps + 256, Pp + 256);

    float4 cv = make_float4(sigf(pi.x) * tanha(pu.x), sigf(pi.y) * tanha(pu.y),
                            sigf(pi.z) * tanha(pu.z), sigf(pi.w) * tanha(pu.w));
    float4 hv = make_float4(sigf(po.x) * tanha(cv.x), sigf(po.y) * tanha(cv.y),
                            sigf(po.z) * tanha(cv.z), sigf(po.w) * tanha(cv.w));
    *(float4*)&g_c[g * 128 + q * 4] = cv;
    uint2 hw = make_uint2(packh2(hv.x, hv.y), packh2(hv.z, hv.w));
    *(uint2*)&g_hH[g * 64 + q * 2] = hw;
}

// B fragment load helper
#define LDB(NF, KS, V) \
    V = *(const uint2*)&g_Upk[(((NF)) * 8 + (KS)) * 64 + 2 * lane]

// ---------------------------------------------------------------------------
// K2: persistent per-tree kernel, fp16 m16n8k16 MMA + ldmatrix A loads +
// register-pipelined B fragments.
// ---------------------------------------------------------------------------
__global__ __launch_bounds__(256, 2) void k2_tree(
    const void* __restrict__ feats,
    float* __restrict__ out)
{
    extern __shared__ unsigned smu[];
    unsigned* sHL = smu;
    unsigned* sHR = smu + 64 * PAD2;

    __shared__ int sg[BM], sgl[BM], sgr[BM], stok[BM], ssrt[BM], spos[BM];

    int tid  = threadIdx.x;
    int lane = tid & 31;
    int w    = tid >> 5;
    int g4   = lane >> 2, tg = lane & 3;
    int tb   = blockIdx.x * NPT;       // tree base node

    // ldmatrix per-lane address component: row = lane&15, col-half = lane>>4
    uint32_t smbase = (uint32_t)__cvta_generic_to_shared(smu);
    uint32_t lmoff  = (((lane & 15) * PAD2) + (lane >> 4) * 4) * 4;
    uint32_t lmL    = smbase + lmoff;                       // into sHL
    uint32_t lmR    = smbase + 64 * PAD2 * 4 + lmoff;       // into sHR

    // Prime the B pipeline (cgi=0, ks=0 position)
    uint2 Bi, Bo, Bu, Bf;
    LDB(w,      0, Bi);
    LDB(16 + w, 0, Bo);
    LDB(32 + w, 0, Bu);
    LDB(48 + w, 0, Bf);

    for (int l = 1; l <= 10; l++) {
        int cnt = (l == 1) ? 1 : (1 << (10 - l));
        int beg = (l == 1) ? 511 : cnt - 1;

        for (int ch = 0; ch < cnt; ch += BM) {
            int n = cnt - ch; if (n > BM) n = BM;

            __syncthreads();
            if (tid < BM) {
                int m = (tid < n) ? tid : 0;
                int i = beg + ch + m;
                int g = tb + i;
                sg[tid]  = g;
                sgl[tid] = tb + 2 * i + 1;
                int rr2 = 2 * i + 2;
                sgr[tid] = (rr2 < NPT) ? tb + rr2 : -1;
                int3 ft = getfeat(feats, g);
                stok[tid] = ft.x;
                ssrt[tid] = ft.y;
                spos[tid] = ft.z;
            }
            __syncthreads();

            // Stage child h tiles (fp16 pair words)
#pragma unroll
            for (int r4 = 0; r4 < 4; r4++) {
                int idx = tid + r4 * 256;
                int m = idx >> 4, q = idx & 15;
                uint4 hl = *(const uint4*)&g_hH[sgl[m] * 64 + q * 4];
                uint4 hr = make_uint4(0u, 0u, 0u, 0u);
                int gr = sgr[m];
                if (gr >= 0) hr = *(const uint4*)&g_hH[gr * 64 + q * 4];
                *(uint4*)&sHL[m * PAD2 + q * 4] = hl;
                *(uint4*)&sHR[m * PAD2 + q * 4] = hr;
            }
            __syncthreads();

#pragma unroll 1
            for (int cgi = 0; cgi < 2; cgi++) {
                int cg = w + 8 * cgi;

                float accI[4][4], accO[4][4], accU[4][4], accFL[4][4], accFR[4][4];
#pragma unroll
                for (int mt = 0; mt < 4; mt++)
#pragma unroll
                    for (int e = 0; e < 4; e++) {
                        accI[mt][e] = accO[mt][e] = accU[mt][e] = 0.0f;
                        accFL[mt][e] = accFR[mt][e] = 0.0f;
                    }

#pragma unroll 1
                for (int ks = 0; ks < 8; ks++) {
                    int np = (cgi * 8 + ks + 1) & 15;
                    int ncg = w + 8 * (np >> 3), nks = np & 7;
                    uint2 Ni, No, Nu, Nf;
                    LDB(ncg,      nks, Ni);
                    LDB(16 + ncg, nks, No);
                    LDB(32 + ncg, nks, Nu);
                    LDB(48 + ncg, nks, Nf);

#pragma unroll
                    for (int mt = 0; mt < 4; mt++) {
                        if (mt * 16 < n) {
                            uint32_t toff = (mt * 16 * PAD2 + 8 * ks) * 4;
                            unsigned l0, l1, l2, l3, r0, r1, r2, r3;
                            ldsm4(l0, l1, l2, l3, lmL + toff);
                            ldsm4(r0, r1, r2, r3, lmR + toff);
                            unsigned s0 = addh2(l0, r0), s1 = addh2(l1, r1);
                            unsigned s2 = addh2(l2, r2), s3 = addh2(l3, r3);
                            MMA16(accI[mt], s0, s1, s2, s3, Bi);
                            MMA16(accO[mt], s0, s1, s2, s3, Bo);
                            MMA16(accU[mt], s0, s1, s2, s3, Bu);
                            MMA16(accFL[mt], l0, l1, l2, l3, Bf);
                            MMA16(accFR[mt], r0, r1, r2, r3, Bf);
                        }
                    }
                    Bi = Ni; Bo = No; Bu = Nu; Bf = Nf;
                }

                int c0 = cg * 8 + 2 * tg;
#pragma unroll
                for (int mt = 0; mt < 4; mt++)
#pragma unroll
                    for (int rr = 0; rr < 2; rr++) {
                        int m = mt * 16 + rr * 8 + g4;
                        if (m >= n) continue;
                        int a = rr * 2;
                        const __half* Tt = g_Ttok  + stok[m] * TCOLS + c0;
                        const __half* Ts = g_Tsort + ssrt[m] * TCOLS + c0;
                        const __half* Tp = g_Tpos  + spos[m] * TCOLS + c0;

                        float2 pi = tbl3v2(Tt,       Ts,       Tp);
                        float2 po = tbl3v2(Tt + 128, Ts + 128, Tp + 128);
                        float2 pu = tbl3v2(Tt + 256, Ts + 256, Tp + 256);
                        float2 pf = tbl3v2(Tt + 384, Ts + 384, Tp + 384);

                        float2 cl = *(const float2*)&g_c[sgl[m] * 128 + c0];
                        float2 cr = make_float2(0.f, 0.f);
                        int gr = sgr[m];
                        if (gr >= 0) cr = *(const float2*)&g_c[gr * 128 + c0];

                        float cx = sigf(accI[mt][a]   + pi.x) * tanha(accU[mt][a]   + pu.x)
                                 + sigf(accFL[mt][a]  + pf.x) * cl.x
                                 + sigf(accFR[mt][a]  + pf.x) * cr.x;
                        float cy = sigf(accI[mt][a+1] + pi.y) * tanha(accU[mt][a+1] + pu.y)
                                 + sigf(accFL[mt][a+1] + pf.y) * cl.y
                                 + sigf(accFR[mt][a+1] + pf.y) * cr.y;
                        float hx = sigf(accO[mt][a]   + po.x) * tanha(cx);
                        float hy = sigf(accO[mt][a+1] + po.y) * tanha(cy);

                        int gg = sg[m];
                        *(float2*)&g_c[gg * 128 + c0] = make_float2(cx, cy);
                        g_hH[gg * 64 + (c0 >> 1)] = packh2(hx, hy);
                        if (l == 10)
                            *(float2*)&out[(gg >> 10) * 128 + c0] = make_float2(hx, hy);
                    }
            }
        }
    }
}

// ---------------------------------------------------------------------------
extern "C" void kernel_launch(void* const* d_in, const int* in_sizes, int n_in,
                              void* d_out, int out_size)
{
    const void* feats  = d_in[0];
    const float* emb   = (const float*)d_in[4];
    const float* sortt = (const float*)d_in[5];
    const float* pe    = (const float*)d_in[6];
    const float* Wiou  = (const float*)d_in[7];
    const float* Uiou  = (const float*)d_in[8];
    const float* biou  = (const float*)d_in[9];
    const float* Wf    = (const float*)d_in[10];
    const float* Uf    = (const float*)d_in[11];
    const float* bf    = (const float*)d_in[12];
    float* out = (float*)d_out;

    cudaFuncSetAttribute(k2_tree, cudaFuncAttributeMaxDynamicSharedMemorySize, SMEMSZ);

    k0a_pack_detect<<<129, 256>>>(Uiou, Uf, (const int*)feats);
    k0_tables<<<761, 512>>>(emb, sortt, pe, Wiou, Wf, biou, bf);
    k1_leaves<<<16384, 256>>>(feats);
    k2_tree<<<NTREES, 256, SMEMSZ>>>(feats, out);
}